// round 12
// baseline (speedup 1.0000x reference)
#include <cuda_runtime.h>
#include <cuda_fp16.h>
#include <math.h>
#include <stdint.h>

// ---------------- problem-size constants (fixed dataset) ----------------
#define NMAX   50000
#define EMAX   300000
#define Dm     128
#define Hh     8
#define DHd    16

// ---------------- scratch (static device memory; no allocations) --------
__device__ float  g_xn  [NMAX * Dm];       // fp32 (MODE1 epilogue)
__device__ __half g_xnh [NMAX * Dm];       // fp16 copy (GEMM A)
__device__ float  g_q   [NMAX * Dm];
// g_kv layout per node (512 halves): [f-block 256][g-block 256].
// Within a block, lane l (l=0..31) owns halves [l*8, l*8+8):
//   [0:4) = k cols l*4..l*4+3,  [4:8) = v cols l*4..l*4+3.
__device__ __half g_kv  [NMAX * 512];
__device__ __half g_gacth[NMAX * Dm];
__device__ float  g_x1  [NMAX * Dm];
__device__ __half g_xn2h[NMAX * Dm];
__device__ __half g_hidh[NMAX * 4 * Dm];
__device__ __half g_WbigTh[640 * Dm];      // [n][k] fp16
__device__ __half g_outwTh[Dm * Dm];       // [n][k]
__device__ __half g_w1Th  [512 * Dm];      // [n][k]
__device__ __half g_w2Th  [Dm * 512];      // [n][k]
__device__ float  g_bbig [640];
__device__ int    g_count [NMAX];
__device__ int    g_offs  [NMAX + 1];
__device__ int    g_cursor[NMAX];
__device__ int    g_entries[2 * EMAX];

__device__ __forceinline__ float gelu_exact(float v) {
    return v * 0.5f * (1.0f + erff(v * 0.70710678118654752440f));
}

__device__ __forceinline__ uint32_t cvta_s(const void* p) {
    uint32_t a;
    asm("{ .reg .u64 t; cvta.to.shared.u64 t, %1; cvt.u32.u64 %0, t; }"
        : "=r"(a) : "l"(p));
    return a;
}

__device__ __forceinline__ void ldm4(uint32_t r[4], uint32_t addr) {
    asm volatile("ldmatrix.sync.aligned.m8n8.x4.shared.b16 {%0,%1,%2,%3}, [%4];"
                 : "=r"(r[0]), "=r"(r[1]), "=r"(r[2]), "=r"(r[3]) : "r"(addr));
}

__device__ __forceinline__ void mma168(float c[4], const uint32_t a[4],
                                       uint32_t b0, uint32_t b1) {
    asm volatile(
        "mma.sync.aligned.m16n8k16.row.col.f32.f16.f16.f32 "
        "{%0,%1,%2,%3}, {%4,%5,%6,%7}, {%8,%9}, {%0,%1,%2,%3};"
        : "+f"(c[0]), "+f"(c[1]), "+f"(c[2]), "+f"(c[3])
        : "r"(a[0]), "r"(a[1]), "r"(a[2]), "r"(a[3]), "r"(b0), "r"(b1));
}

// ---------------- LayerNorm (LN1 only): one warp per row ----------------
__global__ void ln_kernel(const float* __restrict__ xin,
                          const float* __restrict__ g,
                          const float* __restrict__ b, int N)
{
    int warp = (blockIdx.x * blockDim.x + threadIdx.x) >> 5;
    int lane = threadIdx.x & 31;
    if (warp >= N) return;
    float4 v = *reinterpret_cast<const float4*>(xin + (size_t)warp * Dm + lane * 4);
    float s = v.x + v.y + v.z + v.w;
    #pragma unroll
    for (int o = 16; o; o >>= 1) s += __shfl_xor_sync(0xffffffffu, s, o);
    float mu = s * (1.0f / 128.0f);
    float dx = v.x - mu, dy = v.y - mu, dz = v.z - mu, dw = v.w - mu;
    float s2 = dx * dx + dy * dy + dz * dz + dw * dw;
    #pragma unroll
    for (int o = 16; o; o >>= 1) s2 += __shfl_xor_sync(0xffffffffu, s2, o);
    float r = rsqrtf(s2 * (1.0f / 128.0f) + 1e-5f);
    float4 gg = *reinterpret_cast<const float4*>(g + lane * 4);
    float4 bb = *reinterpret_cast<const float4*>(b + lane * 4);
    float4 o4 = make_float4(dx * r * gg.x + bb.x, dy * r * gg.y + bb.y,
                            dz * r * gg.z + bb.z, dw * r * gg.w + bb.w);
    *reinterpret_cast<float4*>(g_xn + (size_t)warp * Dm + lane * 4) = o4;
    __half2 h0 = __floats2half2_rn(o4.x, o4.y);
    __half2 h1 = __floats2half2_rn(o4.z, o4.w);
    __half2* dst = reinterpret_cast<__half2*>(g_xnh + (size_t)warp * Dm + lane * 4);
    dst[0] = h0; dst[1] = h1;
}

// ---------- fold per-head relation matrices into projection weights ------
__global__ void prep_w_kernel(const float* __restrict__ kqv_w,
                              const float* __restrict__ kqv_b,
                              const float* __restrict__ a_f,
                              const float* __restrict__ m_f,
                              const float* __restrict__ p_f,
                              const float* __restrict__ a_g,
                              const float* __restrict__ m_g,
                              const float* __restrict__ p_g)
{
    int idx = blockIdx.x * blockDim.x + threadIdx.x;
    if (idx >= Dm * 640) return;
    int n = idx % 640;
    int k = idx / 640;
    float val;
    if (n < 128) {
        val = kqv_w[k * 384 + 128 + n];         // q block
        if (k == 0) g_bbig[n] = kqv_b[128 + n];
    } else {
        int gsel = (n - 128) >> 7;              // 0:kf 1:vf 2:kg 3:vg
        int c = (n - 128) & 127;
        int h = c >> 4, f = c & 15;
        const float* mat; int srcoff; float scale = 1.0f;
        if      (gsel == 0) { mat = a_f; srcoff = 0;   scale = p_f[h] * 0.25f; }
        else if (gsel == 1) { mat = m_f; srcoff = 256; }
        else if (gsel == 2) { mat = a_g; srcoff = 0;   scale = p_g[h] * 0.25f; }
        else                { mat = m_g; srcoff = 256; }
        float s = 0.0f, bs = 0.0f;
        #pragma unroll
        for (int d = 0; d < 16; d++) {
            float w = mat[h * 256 + d * 16 + f];
            s  += kqv_w[k * 384 + srcoff + h * 16 + d] * w;
            bs += kqv_b[srcoff + h * 16 + d] * w;
        }
        val = s * scale;
        if (k == 0) g_bbig[n] = bs * scale;
    }
    g_WbigTh[n * Dm + k] = __float2half_rn(val);
}

// ---------- transpose + fp16-round the other weights --------------------
__global__ void prep2_kernel(const float* __restrict__ out_w,
                             const float* __restrict__ w1,
                             const float* __restrict__ w2)
{
    int idx = blockIdx.x * blockDim.x + threadIdx.x;
    if (idx < 128 * 128) {
        int n = idx >> 7, k = idx & 127;
        g_outwTh[n * 128 + k] = __float2half_rn(out_w[k * 128 + n]);
    }
    idx -= 128 * 128;
    if (idx >= 0 && idx < 512 * 128) {
        int n = idx >> 7, k = idx & 127;          // n in [0,512), k in [0,128)
        g_w1Th[n * 128 + k] = __float2half_rn(w1[k * 512 + n]);
    }
    idx -= 512 * 128;
    if (idx >= 0 && idx < 128 * 512) {
        int n = idx >> 9, k = idx & 511;          // n in [0,128), k in [0,512)
        g_w2Th[n * 512 + k] = __float2half_rn(w2[k * 128 + n]);
    }
}

// ---------------- CSR build: count / scan / scatter ---------------------
__global__ void zero_count_kernel(int N)
{
    int i = blockIdx.x * blockDim.x + threadIdx.x;
    if (i < N) g_count[i] = 0;
}

__global__ void count_kernel(const int* __restrict__ ef,
                             const int* __restrict__ eg, int E)
{
    int i = blockIdx.x * blockDim.x + threadIdx.x;
    if (i >= 2 * E) return;
    int dst = (i < E) ? ef[E + i] : eg[E + (i - E)];
    atomicAdd(&g_count[dst], 1);
}

__global__ void scan_kernel(int N)
{
    __shared__ int sm[1024];
    int t = threadIdx.x;
    int chunk = (N + 1023) >> 10;
    int b0 = t * chunk;
    int b1 = min(b0 + chunk, N);
    int s = 0;
    for (int i = b0; i < b1; i++) s += g_count[i];
    sm[t] = s;
    __syncthreads();
    for (int off = 1; off < 1024; off <<= 1) {
        int v = (t >= off) ? sm[t - off] : 0;
        __syncthreads();
        sm[t] += v;
        __syncthreads();
    }
    int run = sm[t] - s;    // exclusive prefix
    for (int i = b0; i < b1; i++) {
        g_offs[i] = run;
        g_cursor[i] = run;
        run += g_count[i];
    }
    if (t == 1023) g_offs[N] = sm[1023];
}

__global__ void scatter_kernel(const int* __restrict__ ef,
                               const int* __restrict__ eg, int E)
{
    int i = blockIdx.x * blockDim.x + threadIdx.x;
    if (i >= 2 * E) return;
    int src, dst, tbit;
    if (i < E) { src = ef[i];       dst = ef[E + i];       tbit = 0; }
    else       { int j = i - E; src = eg[j]; dst = eg[E + j]; tbit = 1 << 17; }
    int pos = atomicAdd(&g_cursor[dst], 1);
    g_entries[pos] = src | tbit;
}

// ------------- fused segment-softmax + aggregation + GELU ---------------
__global__ void agg_kernel(int N)
{
    int warp = (blockIdx.x * blockDim.x + threadIdx.x) >> 5;
    int lane = threadIdx.x & 31;
    if (warp >= N) return;
    float4 q4 = *reinterpret_cast<const float4*>(g_q + (size_t)warp * Dm + lane * 4);
    float4 acc = make_float4(0.f, 0.f, 0.f, 0.f);
    float denom = 0.0f;
    int beg = g_offs[warp], end = g_offs[warp + 1];
    int j = beg;
    int loff = lane * 8;
    for (; j + 4 <= end; j += 4) {
        uint4 r[4];
        #pragma unroll
        for (int u = 0; u < 4; u++) {
            int e = g_entries[j + u];
            const __half* p = g_kv + ((size_t)(e & 0x1FFFF) << 9)
                                   + ((e >> 9) & 256) + loff;
            r[u] = *reinterpret_cast<const uint4*>(p);
        }
        float ps[4];
        #pragma unroll
        for (int u = 0; u < 4; u++) {
            float2 ka = __half22float2(*reinterpret_cast<__half2*>(&r[u].x));
            float2 kb = __half22float2(*reinterpret_cast<__half2*>(&r[u].y));
            ps[u] = q4.x * ka.x + q4.y * ka.y + q4.z * kb.x + q4.w * kb.y;
        }
        #pragma unroll
        for (int u = 0; u < 4; u++) {
            ps[u] += __shfl_xor_sync(0xffffffffu, ps[u], 1);
            ps[u] += __shfl_xor_sync(0xffffffffu, ps[u], 2);
        }
        #pragma unroll
        for (int u = 0; u < 4; u++) {
            float w = __expf(ps[u]);
            denom += w;
            float2 va = __half22float2(*reinterpret_cast<__half2*>(&r[u].z));
            float2 vb = __half22float2(*reinterpret_cast<__half2*>(&r[u].w));
            acc.x += w * va.x; acc.y += w * va.y;
            acc.z += w * vb.x; acc.w += w * vb.y;
        }
    }
    for (; j < end; j++) {
        int e = g_entries[j];
        const __half* p = g_kv + ((size_t)(e & 0x1FFFF) << 9)
                               + ((e >> 9) & 256) + loff;
        uint4 r = *reinterpret_cast<const uint4*>(p);
        float2 ka = __half22float2(*reinterpret_cast<__half2*>(&r.x));
        float2 kb = __half22float2(*reinterpret_cast<__half2*>(&r.y));
        float ps = q4.x * ka.x + q4.y * ka.y + q4.z * kb.x + q4.w * kb.y;
        ps += __shfl_xor_sync(0xffffffffu, ps, 1);
        ps += __shfl_xor_sync(0xffffffffu, ps, 2);
        float w = __expf(ps);
        denom += w;
        float2 va = __half22float2(*reinterpret_cast<__half2*>(&r.z));
        float2 vb = __half22float2(*reinterpret_cast<__half2*>(&r.w));
        acc.x += w * va.x; acc.y += w * va.y;
        acc.z += w * vb.x; acc.w += w * vb.y;
    }
    float rd = 1.0f / (denom + 1e-16f);
    __half2 o0 = __floats2half2_rn(gelu_exact(acc.x * rd), gelu_exact(acc.y * rd));
    __half2 o1 = __floats2half2_rn(gelu_exact(acc.z * rd), gelu_exact(acc.w * rd));
    __half2* dst = reinterpret_cast<__half2*>(g_gacth + (size_t)warp * Dm + lane * 4);
    dst[0] = o0; dst[1] = o1;
}

// =========== fp16 ldmatrix+mma.sync GEMM: C = A[M,K] @ Bt[N,K]^T =========
// 128x128 CTA tile; 256 threads = 8 warps (2Mx4N), warp tile 64x32.
// Mainloop: ldmatrix.m8n8.x4 operand loads + mma.sync.m16n8k16.
// MODE 0: A=g_xnh,  Bt=g_WbigTh -> q(fp32) / interleaved g_kv  K=128, 5 nt
// MODE 1: A=g_gacth,Bt=g_outwTh -> g_x1 + FUSED LN2 -> g_xn2h  K=128
// MODE 2: A=g_xn2h, Bt=g_w1Th   -> g_hidh = gelu(C+b1) fp16   K=128, 4 nt
// MODE 3: A=g_hidh, Bt=g_w2Th   -> out = g_x1 + C + b2        K=512
#define APADH 136                          // halves per row (stride)
#define CPAD  132                          // floats per row for C overlay
#define SMEM_BYTES (2 * 128 * APADH * 2)   // 69632 bytes

template <int MODE, int K>
__global__ void __launch_bounds__(256, 2)
wgemm_kernel(const float* __restrict__ bias,
             const float* __restrict__ aux,    // MODE1: x
             const float* __restrict__ skip,   // MODE1 only
             const float* __restrict__ lng,    // MODE1: ln2 gamma
             const float* __restrict__ lnb,    // MODE1: ln2 beta
             float* __restrict__ outp,         // MODE3: d_out
             int M)
{
    extern __shared__ char smem[];
    __half* sA = reinterpret_cast<__half*>(smem);
    __half* sB = reinterpret_cast<__half*>(smem) + 128 * APADH;
    float*  sC = reinterpret_cast<float*>(smem);

    int tid = threadIdx.x;
    int wid = tid >> 5;
    int lane = tid & 31;
    int m0 = blockIdx.x * 128;
    int n0 = blockIdx.y * 128;

    int wm = (wid & 1) * 64;             // 2 M groups of 64 rows
    int wn = (wid >> 1) * 32;            // 4 N groups of 32 cols

    const __half* A;
    const __half* Bt;
    if      (MODE == 0) { A = g_xnh;   Bt = g_WbigTh; }
    else if (MODE == 1) { A = g_gacth; Bt = g_outwTh; }
    else if (MODE == 2) { A = g_xn2h;  Bt = g_w1Th;   }
    else                { A = g_hidh;  Bt = g_w2Th;   }

    float acc[4][4][4];                  // [mi][nj(n8)][frag]
    #pragma unroll
    for (int i = 0; i < 4; i++)
        #pragma unroll
        for (int j = 0; j < 4; j++)
            #pragma unroll
            for (int f = 0; f < 4; f++) acc[i][j][f] = 0.0f;

    // per-lane ldmatrix base addresses (byte offsets into smem)
    uint32_t sAu = cvta_s(sA);
    uint32_t sBu = cvta_s(sB);
    uint32_t a_base = sAu + (uint32_t)(((wm + (lane & 15)) * APADH
                                       + ((lane >> 4) << 3)) * 2);
    int brow = (lane & 7) | (((lane >> 4) & 1) << 3);
    uint32_t b_base = sBu + (uint32_t)(((wn + brow) * APADH
                                       + (((lane >> 3) & 1) << 3)) * 2);

    for (int kc = 0; kc < K; kc += 128) {
        // ---- stage A and B fp16 tiles (8-half vector copies) ----
        #pragma unroll
        for (int i = tid; i < 128 * 16; i += 256) {
            int row = i >> 4, g8 = i & 15;
            int gm = m0 + row;
            uint4 av = make_uint4(0u, 0u, 0u, 0u);
            if (gm < M)
                av = *reinterpret_cast<const uint4*>(A + (size_t)gm * K + kc + g8 * 8);
            *reinterpret_cast<uint4*>(&sA[row * APADH + g8 * 8]) = av;
            uint4 bv = *reinterpret_cast<const uint4*>(
                Bt + (size_t)(n0 + row) * K + kc + g8 * 8);
            *reinterpret_cast<uint4*>(&sB[row * APADH + g8 * 8]) = bv;
        }
        __syncthreads();

        // ---- 8 k16-steps: ldmatrix + mma.m16n8k16 ----
        #pragma unroll
        for (int ks = 0; ks < 8; ks++) {
            uint32_t Af[4][4];
            #pragma unroll
            for (int mi = 0; mi < 4; mi++)
                ldm4(Af[mi], a_base + (uint32_t)(mi * 16 * APADH * 2 + ks * 32));
            uint32_t Bf[2][4];
            #pragma unroll
            for (int j = 0; j < 2; j++)
                ldm4(Bf[j], b_base + (uint32_t)(j * 16 * APADH * 2 + ks * 32));
            #pragma unroll
            for (int mi = 0; mi < 4; mi++) {
                mma168(acc[mi][0], Af[mi], Bf[0][0], Bf[0][1]);
                mma168(acc[mi][1], Af[mi], Bf[0][2], Bf[0][3]);
                mma168(acc[mi][2], Af[mi], Bf[1][0], Bf[1][1]);
                mma168(acc[mi][3], Af[mi], Bf[1][2], Bf[1][3]);
            }
        }
        __syncthreads();
    }

    // ---- dump C tile into float overlay ----
    {
        int g = lane >> 2, t = lane & 3;
        #pragma unroll
        for (int mi = 0; mi < 4; mi++) {
            #pragma unroll
            for (int nj = 0; nj < 4; nj++) {
                int col = wn + nj * 8 + t * 2;
                int r0 = wm + mi * 16 + g;
                *reinterpret_cast<float2*>(&sC[r0 * CPAD + col]) =
                    make_float2(acc[mi][nj][0], acc[mi][nj][1]);
                *reinterpret_cast<float2*>(&sC[(r0 + 8) * CPAD + col]) =
                    make_float2(acc[mi][nj][2], acc[mi][nj][3]);
            }
        }
    }
    __syncthreads();

    if (MODE == 1) {
        // fused epilogue: x1 = x + sig*(C+b) + (1-sig)*xn ; then LN2 -> g_xn2h
        float sig = 1.0f / (1.0f + __expf(-skip[0]));
        float om = 1.0f - sig;
        float4 bb  = *reinterpret_cast<const float4*>(bias + lane * 4);
        float4 gg  = *reinterpret_cast<const float4*>(lng + lane * 4);
        float4 be  = *reinterpret_cast<const float4*>(lnb + lane * 4);
        for (int r = wid; r < 128; r += 8) {
            int gm = m0 + r;
            if (gm >= M) continue;
            float4 v = *reinterpret_cast<float4*>(&sC[r * CPAD + lane * 4]);
            float4 xv = *reinterpret_cast<const float4*>(aux + (size_t)gm * Dm + lane * 4);
            float4 xn = *reinterpret_cast<const float4*>(g_xn + (size_t)gm * Dm + lane * 4);
            v.x = xv.x + sig * (v.x + bb.x) + om * xn.x;
            v.y = xv.y + sig * (v.y + bb.y) + om * xn.y;
            v.z = xv.z + sig * (v.z + bb.z) + om * xn.z;
            v.w = xv.w + sig * (v.w + bb.w) + om * xn.w;
            *reinterpret_cast<float4*>(g_x1 + (size_t)gm * Dm + lane * 4) = v;
            // LN over the row
            float s = v.x + v.y + v.z + v.w;
            #pragma unroll
            for (int o = 16; o; o >>= 1) s += __shfl_xor_sync(0xffffffffu, s, o);
            float mu = s * (1.0f / 128.0f);
            float dx = v.x - mu, dy = v.y - mu, dz = v.z - mu, dw = v.w - mu;
            float s2 = dx * dx + dy * dy + dz * dz + dw * dw;
            #pragma unroll
            for (int o = 16; o; o >>= 1) s2 += __shfl_xor_sync(0xffffffffu, s2, o);
            float rr = rsqrtf(s2 * (1.0f / 128.0f) + 1e-5f);
            __half2 h0 = __floats2half2_rn(dx * rr * gg.x + be.x, dy * rr * gg.y + be.y);
            __half2 h1 = __floats2half2_rn(dz * rr * gg.z + be.z, dw * rr * gg.w + be.w);
            __half2* dst = reinterpret_cast<__half2*>(g_xn2h + (size_t)gm * Dm + lane * 4);
            dst[0] = h0; dst[1] = h1;
        }
        return;
    }

    #pragma unroll
    for (int i = tid; i < 128 * 32; i += 256) {
        int row = i >> 5, q = i & 31;
        int gm = m0 + row;
        if (gm >= M) continue;
        float4 v = *reinterpret_cast<float4*>(&sC[row * CPAD + q * 4]);
        int gn = n0 + q * 4;
        if (MODE == 0) {
            float4 bb = *reinterpret_cast<const float4*>(g_bbig + gn);
            v.x += bb.x; v.y += bb.y; v.z += bb.z; v.w += bb.w;
            if (blockIdx.y == 0) {
                *reinterpret_cast<float4*>(g_q + (size_t)gm * Dm + q * 4) = v;
            } else {
                // interleaved kv layout: type 0..3 = kf,vf,kg,vg
                int type = blockIdx.y - 1;
                int tb = (type >> 1) * 256;     // f or g block
                int koff = (type & 1) * 4;      // k at +0, v at +4
                __half2 h0 = __floats2half2_rn(v.x, v.y);
                __half2 h1 = __floats2half2_rn(v.z, v.w);
                __half* base = g_kv + ((size_t)gm << 9) + tb + q * 8 + koff;
                *reinterpret_cast<__half2*>(base) = h0;
                *reinterpret_cast<__half2*>(base + 2) = h1;
            }
        } else if (MODE == 2) {
            float4 bb = *reinterpret_cast<const float4*>(bias + gn);
            __half2 h0 = __floats2half2_rn(gelu_exact(v.x + bb.x), gelu_exact(v.y + bb.y));
            __half2 h1 = __floats2half2_rn(gelu_exact(v.z + bb.z), gelu_exact(v.w + bb.w));
            __half2* dst = reinterpret_cast<__half2*>(
                g_hidh + (size_t)gm * 512 + gn);
            dst[0] = h0; dst[1] = h1;
        } else {
            float4 bb = *reinterpret_cast<const float4*>(bias + gn);
            float4 x1 = *reinterpret_cast<const float4*>(g_x1 + (size_t)gm * Dm + gn);
            v.x = x1.x + v.x + bb.x;
            v.y = x1.y + v.y + bb.y;
            v.z = x1.z + v.z + bb.z;
            v.w = x1.w + v.w + bb.w;
            *reinterpret_cast<float4*>(outp + (size_t)gm * Dm + gn) = v;
        }
    }
}

// ------------------------------- launch ---------------------------------
extern "C" void kernel_launch(void* const* d_in, const int* in_sizes, int n_in,
                              void* d_out, int out_size)
{
    const float* x      = (const float*)d_in[0];
    const int*   ef     = (const int*)  d_in[1];
    const int*   eg     = (const int*)  d_in[2];
    const float* kqv_w  = (const float*)d_in[3];
    const float* kqv_b  = (const float*)d_in[4];
    const float* a_f    = (const float*)d_in[5];
    const float* m_f    = (const float*)d_in[6];
    const float* p_f    = (const float*)d_in[7];
    const float* a_g    = (const float*)d_in[8];
    const float* m_g    = (const float*)d_in[9];
    const float* p_g    = (const float*)d_in[10];
    const float* out_w  = (const float*)d_in[11];
    const float* out_b  = (const float*)d_in[12];
    const float* skip   = (const float*)d_in[13];
    const float* ln1_g  = (const float*)d_in[14];
    const float* ln1_b  = (const float*)d_in[15];
    const float* ln2_g  = (const float*)d_in[16];
    const float* ln2_b  = (const float*)d_in[17];
    const float* w1     = (const float*)d_in[18];
    const float* b1     = (const float*)d_in[19];
    const float* w2     = (const float*)d_in[20];
    const float* b2     = (const float*)d_in[21];
    float* out = (float*)d_out;

    int N = in_sizes[0] / Dm;
    int E = in_sizes[1] / 2;
    if (N > NMAX) N = NMAX;
    if (E > EMAX) E = EMAX;

    int mtiles = (N + 127) / 128;

    cudaFuncSetAttribute(wgemm_kernel<0, 128>, cudaFuncAttributeMaxDynamicSharedMemorySize, SMEM_BYTES);
    cudaFuncSetAttribute(wgemm_kernel<1, 128>, cudaFuncAttributeMaxDynamicSharedMemorySize, SMEM_BYTES);
    cudaFuncSetAttribute(wgemm_kernel<2, 128>, cudaFuncAttributeMaxDynamicSharedMemorySize, SMEM_BYTES);
    cudaFuncSetAttribute(wgemm_kernel<3, 512>, cudaFuncAttributeMaxDynamicSharedMemorySize, SMEM_BYTES);

    // 0. LN1: x -> g_xn + g_xnh
    ln_kernel<<<(N + 7) / 8, 256>>>(x, ln1_g, ln1_b, N);
    // 1. fold relation matrices into WbigTh/bbig (transposed, fp16)
    prep_w_kernel<<<(Dm * 640 + 255) / 256, 256>>>(kqv_w, kqv_b, a_f, m_f, p_f,
                                                   a_g, m_g, p_g);
    // 2. transpose + convert remaining weights
    prep2_kernel<<<(147456 + 255) / 256, 256>>>(out_w, w1, w2);
    // 3. fused projection GEMM: q + interleaved kv
    wgemm_kernel<0, 128><<<dim3(mtiles, 5), 256, SMEM_BYTES>>>(
        nullptr, nullptr, nullptr, nullptr, nullptr, nullptr, N);
    // 4-7. CSR build by dst
    zero_count_kernel<<<(N + 255) / 256, 256>>>(N);
    count_kernel<<<(2 * E + 255) / 256, 256>>>(ef, eg, E);
    scan_kernel<<<1, 1024>>>(N);
    scatter_kernel<<<(2 * E + 255) / 256, 256>>>(ef, eg, E);
    // 8. fused softmax + aggregation + gelu (1 uint4/edge gather)
    agg_kernel<<<(N + 7) / 8, 256>>>(N);
    // 9. out projection + skip-mix + residual + FUSED LN2 -> g_x1, g_xn2h
    wgemm_kernel<1, 128><<<dim3(mtiles, 1), 256, SMEM_BYTES>>>(
        out_b, x, skip, ln2_g, ln2_b, nullptr, N);
    // 10. FFN up + gelu -> g_hidh (fp16)
    wgemm_kernel<2, 128><<<dim3(mtiles, 4), 256, SMEM_BYTES>>>(
        b1, nullptr, nullptr, nullptr, nullptr, nullptr, N);
    // 11. FFN down + residual -> out
    wgemm_kernel<3, 512><<<dim3(mtiles, 1), 256, SMEM_BYTES>>>(
        b2, nullptr, nullptr, nullptr, nullptr, out, N);
}

// round 13
// speedup vs baseline: 1.0154x; 1.0154x over previous
#include <cuda_runtime.h>
#include <cuda_fp16.h>
#include <math.h>
#include <stdint.h>

// ---------------- problem-size constants (fixed dataset) ----------------
#define NMAX   50000
#define EMAX   300000
#define Dm     128
#define Hh     8
#define DHd    16

// ---------------- scratch (static device memory; no allocations) --------
__device__ float  g_xn  [NMAX * Dm];       // fp32 (MODE1 epilogue)
__device__ __half g_xnh [NMAX * Dm];       // fp16 copy (GEMM A)
__device__ __half g_qh  [NMAX * Dm];       // q, fp16
// g_kv layout per node (512 halves): [f-block 256][g-block 256].
// Within a block, group q (q=0..31) owns halves [q*8, q*8+8):
//   [0:4) = k cols q*4..q*4+3,  [4:8) = v cols q*4..q*4+3.
__device__ __half g_kv  [NMAX * 512];
__device__ __half g_gacth[NMAX * Dm];
__device__ float  g_x1  [NMAX * Dm];
__device__ __half g_xn2h[NMAX * Dm];
__device__ __half g_hidh[NMAX * 4 * Dm];
__device__ __half g_WbigTh[640 * Dm];      // [n][k] fp16
__device__ __half g_outwTh[Dm * Dm];       // [n][k]
__device__ __half g_w1Th  [512 * Dm];      // [n][k]
__device__ __half g_w2Th  [Dm * 512];      // [n][k]
__device__ float  g_bbig [640];
__device__ int    g_count [NMAX];
__device__ int    g_offs  [NMAX + 1];
__device__ int    g_cursor[NMAX];
__device__ int    g_entries[2 * EMAX];

__device__ __forceinline__ float gelu_exact(float v) {
    return v * 0.5f * (1.0f + erff(v * 0.70710678118654752440f));
}

__device__ __forceinline__ uint32_t cvta_s(const void* p) {
    uint32_t a;
    asm("{ .reg .u64 t; cvta.to.shared.u64 t, %1; cvt.u32.u64 %0, t; }"
        : "=r"(a) : "l"(p));
    return a;
}

__device__ __forceinline__ void ldm4(uint32_t r[4], uint32_t addr) {
    asm volatile("ldmatrix.sync.aligned.m8n8.x4.shared.b16 {%0,%1,%2,%3}, [%4];"
                 : "=r"(r[0]), "=r"(r[1]), "=r"(r[2]), "=r"(r[3]) : "r"(addr));
}

__device__ __forceinline__ void mma168(float c[4], const uint32_t a[4],
                                       uint32_t b0, uint32_t b1) {
    asm volatile(
        "mma.sync.aligned.m16n8k16.row.col.f32.f16.f16.f32 "
        "{%0,%1,%2,%3}, {%4,%5,%6,%7}, {%8,%9}, {%0,%1,%2,%3};"
        : "+f"(c[0]), "+f"(c[1]), "+f"(c[2]), "+f"(c[3])
        : "r"(a[0]), "r"(a[1]), "r"(a[2]), "r"(a[3]), "r"(b0), "r"(b1));
}

// ---------------- LayerNorm (LN1 only): one warp per row ----------------
__global__ void ln_kernel(const float* __restrict__ xin,
                          const float* __restrict__ g,
                          const float* __restrict__ b, int N)
{
    int warp = (blockIdx.x * blockDim.x + threadIdx.x) >> 5;
    int lane = threadIdx.x & 31;
    if (warp >= N) return;
    float4 v = *reinterpret_cast<const float4*>(xin + (size_t)warp * Dm + lane * 4);
    float s = v.x + v.y + v.z + v.w;
    #pragma unroll
    for (int o = 16; o; o >>= 1) s += __shfl_xor_sync(0xffffffffu, s, o);
    float mu = s * (1.0f / 128.0f);
    float dx = v.x - mu, dy = v.y - mu, dz = v.z - mu, dw = v.w - mu;
    float s2 = dx * dx + dy * dy + dz * dz + dw * dw;
    #pragma unroll
    for (int o = 16; o; o >>= 1) s2 += __shfl_xor_sync(0xffffffffu, s2, o);
    float r = rsqrtf(s2 * (1.0f / 128.0f) + 1e-5f);
    float4 gg = *reinterpret_cast<const float4*>(g + lane * 4);
    float4 bb = *reinterpret_cast<const float4*>(b + lane * 4);
    float4 o4 = make_float4(dx * r * gg.x + bb.x, dy * r * gg.y + bb.y,
                            dz * r * gg.z + bb.z, dw * r * gg.w + bb.w);
    *reinterpret_cast<float4*>(g_xn + (size_t)warp * Dm + lane * 4) = o4;
    __half2 h0 = __floats2half2_rn(o4.x, o4.y);
    __half2 h1 = __floats2half2_rn(o4.z, o4.w);
    __half2* dst = reinterpret_cast<__half2*>(g_xnh + (size_t)warp * Dm + lane * 4);
    dst[0] = h0; dst[1] = h1;
}

// ---------- fold per-head relation matrices into projection weights ------
__global__ void prep_w_kernel(const float* __restrict__ kqv_w,
                              const float* __restrict__ kqv_b,
                              const float* __restrict__ a_f,
                              const float* __restrict__ m_f,
                              const float* __restrict__ p_f,
                              const float* __restrict__ a_g,
                              const float* __restrict__ m_g,
                              const float* __restrict__ p_g)
{
    int idx = blockIdx.x * blockDim.x + threadIdx.x;
    if (idx >= Dm * 640) return;
    int n = idx % 640;
    int k = idx / 640;
    float val;
    if (n < 128) {
        val = kqv_w[k * 384 + 128 + n];         // q block
        if (k == 0) g_bbig[n] = kqv_b[128 + n];
    } else {
        int gsel = (n - 128) >> 7;              // 0:kf 1:vf 2:kg 3:vg
        int c = (n - 128) & 127;
        int h = c >> 4, f = c & 15;
        const float* mat; int srcoff; float scale = 1.0f;
        if      (gsel == 0) { mat = a_f; srcoff = 0;   scale = p_f[h] * 0.25f; }
        else if (gsel == 1) { mat = m_f; srcoff = 256; }
        else if (gsel == 2) { mat = a_g; srcoff = 0;   scale = p_g[h] * 0.25f; }
        else                { mat = m_g; srcoff = 256; }
        float s = 0.0f, bs = 0.0f;
        #pragma unroll
        for (int d = 0; d < 16; d++) {
            float w = mat[h * 256 + d * 16 + f];
            s  += kqv_w[k * 384 + srcoff + h * 16 + d] * w;
            bs += kqv_b[srcoff + h * 16 + d] * w;
        }
        val = s * scale;
        if (k == 0) g_bbig[n] = bs * scale;
    }
    g_WbigTh[n * Dm + k] = __float2half_rn(val);
}

// ---------- transpose + fp16-round the other weights --------------------
__global__ void prep2_kernel(const float* __restrict__ out_w,
                             const float* __restrict__ w1,
                             const float* __restrict__ w2)
{
    int idx = blockIdx.x * blockDim.x + threadIdx.x;
    if (idx < 128 * 128) {
        int n = idx >> 7, k = idx & 127;
        g_outwTh[n * 128 + k] = __float2half_rn(out_w[k * 128 + n]);
    }
    idx -= 128 * 128;
    if (idx >= 0 && idx < 512 * 128) {
        int n = idx >> 7, k = idx & 127;          // n in [0,512), k in [0,128)
        g_w1Th[n * 128 + k] = __float2half_rn(w1[k * 512 + n]);
    }
    idx -= 512 * 128;
    if (idx >= 0 && idx < 128 * 512) {
        int n = idx >> 9, k = idx & 511;          // n in [0,128), k in [0,512)
        g_w2Th[n * 512 + k] = __float2half_rn(w2[k * 128 + n]);
    }
}

// ---------------- CSR build: count / scan / scatter ---------------------
__global__ void zero_count_kernel(int N)
{
    int i = blockIdx.x * blockDim.x + threadIdx.x;
    if (i < N) g_count[i] = 0;
}

__global__ void count_kernel(const int* __restrict__ ef,
                             const int* __restrict__ eg, int E)
{
    int i = blockIdx.x * blockDim.x + threadIdx.x;
    if (i >= 2 * E) return;
    int dst = (i < E) ? ef[E + i] : eg[E + (i - E)];
    atomicAdd(&g_count[dst], 1);
}

__global__ void scan_kernel(int N)
{
    __shared__ int sm[1024];
    int t = threadIdx.x;
    int chunk = (N + 1023) >> 10;
    int b0 = t * chunk;
    int b1 = min(b0 + chunk, N);
    int s = 0;
    for (int i = b0; i < b1; i++) s += g_count[i];
    sm[t] = s;
    __syncthreads();
    for (int off = 1; off < 1024; off <<= 1) {
        int v = (t >= off) ? sm[t - off] : 0;
        __syncthreads();
        sm[t] += v;
        __syncthreads();
    }
    int run = sm[t] - s;    // exclusive prefix
    for (int i = b0; i < b1; i++) {
        g_offs[i] = run;
        g_cursor[i] = run;
        run += g_count[i];
    }
    if (t == 1023) g_offs[N] = sm[1023];
}

__global__ void scatter_kernel(const int* __restrict__ ef,
                               const int* __restrict__ eg, int E)
{
    int i = blockIdx.x * blockDim.x + threadIdx.x;
    if (i >= 2 * E) return;
    int src, dst, tbit;
    if (i < E) { src = ef[i];       dst = ef[E + i];       tbit = 0; }
    else       { int j = i - E; src = eg[j]; dst = eg[E + j]; tbit = 1 << 17; }
    int pos = atomicAdd(&g_cursor[dst], 1);
    g_entries[pos] = src | tbit;
}

// ------------- fused segment-softmax + aggregation + GELU ---------------
__global__ void agg_kernel(int N)
{
    int warp = (blockIdx.x * blockDim.x + threadIdx.x) >> 5;
    int lane = threadIdx.x & 31;
    if (warp >= N) return;
    uint2 qr = *reinterpret_cast<const uint2*>(g_qh + (size_t)warp * Dm + lane * 4);
    float2 qa = __half22float2(*reinterpret_cast<__half2*>(&qr.x));
    float2 qb = __half22float2(*reinterpret_cast<__half2*>(&qr.y));
    float4 q4 = make_float4(qa.x, qa.y, qb.x, qb.y);
    float4 acc = make_float4(0.f, 0.f, 0.f, 0.f);
    float denom = 0.0f;
    int beg = g_offs[warp], end = g_offs[warp + 1];
    int j = beg;
    int loff = lane * 8;
    for (; j + 4 <= end; j += 4) {
        uint4 r[4];
        #pragma unroll
        for (int u = 0; u < 4; u++) {
            int e = g_entries[j + u];
            const __half* p = g_kv + ((size_t)(e & 0x1FFFF) << 9)
                                   + ((e >> 9) & 256) + loff;
            r[u] = *reinterpret_cast<const uint4*>(p);
        }
        float ps[4];
        #pragma unroll
        for (int u = 0; u < 4; u++) {
            float2 ka = __half22float2(*reinterpret_cast<__half2*>(&r[u].x));
            float2 kb = __half22float2(*reinterpret_cast<__half2*>(&r[u].y));
            ps[u] = q4.x * ka.x + q4.y * ka.y + q4.z * kb.x + q4.w * kb.y;
        }
        #pragma unroll
        for (int u = 0; u < 4; u++) {
            ps[u] += __shfl_xor_sync(0xffffffffu, ps[u], 1);
            ps[u] += __shfl_xor_sync(0xffffffffu, ps[u], 2);
        }
        #pragma unroll
        for (int u = 0; u < 4; u++) {
            float w = __expf(ps[u]);
            denom += w;
            float2 va = __half22float2(*reinterpret_cast<__half2*>(&r[u].z));
            float2 vb = __half22float2(*reinterpret_cast<__half2*>(&r[u].w));
            acc.x += w * va.x; acc.y += w * va.y;
            acc.z += w * vb.x; acc.w += w * vb.y;
        }
    }
    for (; j < end; j++) {
        int e = g_entries[j];
        const __half* p = g_kv + ((size_t)(e & 0x1FFFF) << 9)
                               + ((e >> 9) & 256) + loff;
        uint4 r = *reinterpret_cast<const uint4*>(p);
        float2 ka = __half22float2(*reinterpret_cast<__half2*>(&r.x));
        float2 kb = __half22float2(*reinterpret_cast<__half2*>(&r.y));
        float ps = q4.x * ka.x + q4.y * ka.y + q4.z * kb.x + q4.w * kb.y;
        ps += __shfl_xor_sync(0xffffffffu, ps, 1);
        ps += __shfl_xor_sync(0xffffffffu, ps, 2);
        float w = __expf(ps);
        denom += w;
        float2 va = __half22float2(*reinterpret_cast<__half2*>(&r.z));
        float2 vb = __half22float2(*reinterpret_cast<__half2*>(&r.w));
        acc.x += w * va.x; acc.y += w * va.y;
        acc.z += w * vb.x; acc.w += w * vb.y;
    }
    float rd = 1.0f / (denom + 1e-16f);
    __half2 o0 = __floats2half2_rn(gelu_exact(acc.x * rd), gelu_exact(acc.y * rd));
    __half2 o1 = __floats2half2_rn(gelu_exact(acc.z * rd), gelu_exact(acc.w * rd));
    __half2* dst = reinterpret_cast<__half2*>(g_gacth + (size_t)warp * Dm + lane * 4);
    dst[0] = o0; dst[1] = o1;
}

// =========== fp16 ldmatrix+mma.sync GEMM: C = A[M,K] @ Bt[N,K]^T =========
// 128x128 CTA tile; 256 threads = 8 warps (2Mx4N), warp tile 64x32.
// MODEs 0/2/3: DIRECT register->global epilogue (verified frag layout,
// no smem C round-trip). MODE 1: sC overlay + fused LN2 (needs full rows).
// MODE 0: A=g_xnh,  Bt=g_WbigTh -> qh(fp16) / interleaved g_kv  K=128, 5 nt
// MODE 1: A=g_gacth,Bt=g_outwTh -> g_x1 + FUSED LN2 -> g_xn2h  K=128
// MODE 2: A=g_xn2h, Bt=g_w1Th   -> g_hidh = gelu(C+b1) fp16   K=128, 4 nt
// MODE 3: A=g_hidh, Bt=g_w2Th   -> out = g_x1 + C + b2        K=512
#define APADH 136                          // halves per row (stride)
#define CPAD  132                          // floats per row for C overlay
#define SMEM_BYTES (2 * 128 * APADH * 2)   // 69632 bytes

template <int MODE, int K>
__global__ void __launch_bounds__(256, 2)
wgemm_kernel(const float* __restrict__ bias,
             const float* __restrict__ aux,    // MODE1: x
             const float* __restrict__ skip,   // MODE1 only
             const float* __restrict__ lng,    // MODE1: ln2 gamma
             const float* __restrict__ lnb,    // MODE1: ln2 beta
             float* __restrict__ outp,         // MODE3: d_out
             int M)
{
    extern __shared__ char smem[];
    __half* sA = reinterpret_cast<__half*>(smem);
    __half* sB = reinterpret_cast<__half*>(smem) + 128 * APADH;
    float*  sC = reinterpret_cast<float*>(smem);

    int tid = threadIdx.x;
    int wid = tid >> 5;
    int lane = tid & 31;
    int m0 = blockIdx.x * 128;
    int n0 = blockIdx.y * 128;

    int wm = (wid & 1) * 64;             // 2 M groups of 64 rows
    int wn = (wid >> 1) * 32;            // 4 N groups of 32 cols

    const __half* A;
    const __half* Bt;
    if      (MODE == 0) { A = g_xnh;   Bt = g_WbigTh; }
    else if (MODE == 1) { A = g_gacth; Bt = g_outwTh; }
    else if (MODE == 2) { A = g_xn2h;  Bt = g_w1Th;   }
    else                { A = g_hidh;  Bt = g_w2Th;   }

    float acc[4][4][4];                  // [mi][nj(n8)][frag]
    #pragma unroll
    for (int i = 0; i < 4; i++)
        #pragma unroll
        for (int j = 0; j < 4; j++)
            #pragma unroll
            for (int f = 0; f < 4; f++) acc[i][j][f] = 0.0f;

    // per-lane ldmatrix base addresses (byte offsets into smem)
    uint32_t sAu = cvta_s(sA);
    uint32_t sBu = cvta_s(sB);
    uint32_t a_base = sAu + (uint32_t)(((wm + (lane & 15)) * APADH
                                       + ((lane >> 4) << 3)) * 2);
    int brow = (lane & 7) | (((lane >> 4) & 1) << 3);
    uint32_t b_base = sBu + (uint32_t)(((wn + brow) * APADH
                                       + (((lane >> 3) & 1) << 3)) * 2);

    for (int kc = 0; kc < K; kc += 128) {
        #pragma unroll
        for (int i = tid; i < 128 * 16; i += 256) {
            int row = i >> 4, g8 = i & 15;
            int gm = m0 + row;
            uint4 av = make_uint4(0u, 0u, 0u, 0u);
            if (gm < M)
                av = *reinterpret_cast<const uint4*>(A + (size_t)gm * K + kc + g8 * 8);
            *reinterpret_cast<uint4*>(&sA[row * APADH + g8 * 8]) = av;
            uint4 bv = *reinterpret_cast<const uint4*>(
                Bt + (size_t)(n0 + row) * K + kc + g8 * 8);
            *reinterpret_cast<uint4*>(&sB[row * APADH + g8 * 8]) = bv;
        }
        __syncthreads();

        #pragma unroll
        for (int ks = 0; ks < 8; ks++) {
            uint32_t Af[4][4];
            #pragma unroll
            for (int mi = 0; mi < 4; mi++)
                ldm4(Af[mi], a_base + (uint32_t)(mi * 16 * APADH * 2 + ks * 32));
            uint32_t Bf[2][4];
            #pragma unroll
            for (int j = 0; j < 2; j++)
                ldm4(Bf[j], b_base + (uint32_t)(j * 16 * APADH * 2 + ks * 32));
            #pragma unroll
            for (int mi = 0; mi < 4; mi++) {
                mma168(acc[mi][0], Af[mi], Bf[0][0], Bf[0][1]);
                mma168(acc[mi][1], Af[mi], Bf[0][2], Bf[0][3]);
                mma168(acc[mi][2], Af[mi], Bf[1][0], Bf[1][1]);
                mma168(acc[mi][3], Af[mi], Bf[1][2], Bf[1][3]);
            }
        }
        if (kc + 128 < K) __syncthreads();
    }

    int g = lane >> 2, t = lane & 3;

    if (MODE != 1) {
        // ---- direct register -> global epilogue (no smem C staging) ----
        #pragma unroll
        for (int nj = 0; nj < 4; nj++) {
            int colL = wn + nj * 8 + t * 2;      // local col (even)
            int gn = n0 + colL;
            float2 bb;
            if (MODE == 0) bb = *reinterpret_cast<const float2*>(g_bbig + gn);
            else           bb = *reinterpret_cast<const float2*>(bias + gn);
            #pragma unroll
            for (int mi = 0; mi < 4; mi++) {
                #pragma unroll
                for (int hf = 0; hf < 2; hf++) {
                    int gm = m0 + wm + mi * 16 + g + hf * 8;
                    if (gm >= M) continue;
                    float v0 = acc[mi][nj][hf * 2 + 0] + bb.x;
                    float v1 = acc[mi][nj][hf * 2 + 1] + bb.y;
                    if (MODE == 0) {
                        __half2 h = __floats2half2_rn(v0, v1);
                        if (blockIdx.y == 0) {
                            *reinterpret_cast<__half2*>(
                                g_qh + (size_t)gm * Dm + colL) = h;
                        } else {
                            int type = blockIdx.y - 1;   // kf,vf,kg,vg
                            int tb = (type >> 1) * 256;
                            int koff = (type & 1) * 4;
                            int grp = colL >> 2, win = colL & 3;
                            *reinterpret_cast<__half2*>(
                                g_kv + ((size_t)gm << 9) + tb + grp * 8 + koff + win) = h;
                        }
                    } else if (MODE == 2) {
                        __half2 h = __floats2half2_rn(gelu_exact(v0), gelu_exact(v1));
                        *reinterpret_cast<__half2*>(
                            g_hidh + (size_t)gm * 512 + gn) = h;
                    } else {
                        float2 x1 = *reinterpret_cast<const float2*>(
                            g_x1 + (size_t)gm * Dm + gn);
                        *reinterpret_cast<float2*>(outp + (size_t)gm * Dm + gn) =
                            make_float2(x1.x + v0, x1.y + v1);
                    }
                }
            }
        }
        return;
    }

    // ---- MODE 1: dump C to smem overlay, then fused skip-mix + LN2 ----
    __syncthreads();
    #pragma unroll
    for (int mi = 0; mi < 4; mi++) {
        #pragma unroll
        for (int nj = 0; nj < 4; nj++) {
            int col = wn + nj * 8 + t * 2;
            int r0 = wm + mi * 16 + g;
            *reinterpret_cast<float2*>(&sC[r0 * CPAD + col]) =
                make_float2(acc[mi][nj][0], acc[mi][nj][1]);
            *reinterpret_cast<float2*>(&sC[(r0 + 8) * CPAD + col]) =
                make_float2(acc[mi][nj][2], acc[mi][nj][3]);
        }
    }
    __syncthreads();

    float sig = 1.0f / (1.0f + __expf(-skip[0]));
    float om = 1.0f - sig;
    float4 bb  = *reinterpret_cast<const float4*>(bias + lane * 4);
    float4 gg  = *reinterpret_cast<const float4*>(lng + lane * 4);
    float4 be  = *reinterpret_cast<const float4*>(lnb + lane * 4);
    for (int r = wid; r < 128; r += 8) {
        int gm = m0 + r;
        if (gm >= M) continue;
        float4 v = *reinterpret_cast<float4*>(&sC[r * CPAD + lane * 4]);
        float4 xv = *reinterpret_cast<const float4*>(aux + (size_t)gm * Dm + lane * 4);
        float4 xn = *reinterpret_cast<const float4*>(g_xn + (size_t)gm * Dm + lane * 4);
        v.x = xv.x + sig * (v.x + bb.x) + om * xn.x;
        v.y = xv.y + sig * (v.y + bb.y) + om * xn.y;
        v.z = xv.z + sig * (v.z + bb.z) + om * xn.z;
        v.w = xv.w + sig * (v.w + bb.w) + om * xn.w;
        *reinterpret_cast<float4*>(g_x1 + (size_t)gm * Dm + lane * 4) = v;
        float s = v.x + v.y + v.z + v.w;
        #pragma unroll
        for (int o = 16; o; o >>= 1) s += __shfl_xor_sync(0xffffffffu, s, o);
        float mu = s * (1.0f / 128.0f);
        float dx = v.x - mu, dy = v.y - mu, dz = v.z - mu, dw = v.w - mu;
        float s2 = dx * dx + dy * dy + dz * dz + dw * dw;
        #pragma unroll
        for (int o = 16; o; o >>= 1) s2 += __shfl_xor_sync(0xffffffffu, s2, o);
        float rr = rsqrtf(s2 * (1.0f / 128.0f) + 1e-5f);
        __half2 h0 = __floats2half2_rn(dx * rr * gg.x + be.x, dy * rr * gg.y + be.y);
        __half2 h1 = __floats2half2_rn(dz * rr * gg.z + be.z, dw * rr * gg.w + be.w);
        __half2* dst = reinterpret_cast<__half2*>(g_xn2h + (size_t)gm * Dm + lane * 4);
        dst[0] = h0; dst[1] = h1;
    }
}

// ------------------------------- launch ---------------------------------
extern "C" void kernel_launch(void* const* d_in, const int* in_sizes, int n_in,
                              void* d_out, int out_size)
{
    const float* x      = (const float*)d_in[0];
    const int*   ef     = (const int*)  d_in[1];
    const int*   eg     = (const int*)  d_in[2];
    const float* kqv_w  = (const float*)d_in[3];
    const float* kqv_b  = (const float*)d_in[4];
    const float* a_f    = (const float*)d_in[5];
    const float* m_f    = (const float*)d_in[6];
    const float* p_f    = (const float*)d_in[7];
    const float* a_g    = (const float*)d_in[8];
    const float* m_g    = (const float*)d_in[9];
    const float* p_g    = (const float*)d_in[10];
    const float* out_w  = (const float*)d_in[11];
    const float* out_b  = (const float*)d_in[12];
    const float* skip   = (const float*)d_in[13];
    const float* ln1_g  = (const float*)d_in[14];
    const float* ln1_b  = (const float*)d_in[15];
    const float* ln2_g  = (const float*)d_in[16];
    const float* ln2_b  = (const float*)d_in[17];
    const float* w1     = (const float*)d_in[18];
    const float* b1     = (const float*)d_in[19];
    const float* w2     = (const float*)d_in[20];
    const float* b2     = (const float*)d_in[21];
    float* out = (float*)d_out;

    int N = in_sizes[0] / Dm;
    int E = in_sizes[1] / 2;
    if (N > NMAX) N = NMAX;
    if (E > EMAX) E = EMAX;

    int mtiles = (N + 127) / 128;

    cudaFuncSetAttribute(wgemm_kernel<0, 128>, cudaFuncAttributeMaxDynamicSharedMemorySize, SMEM_BYTES);
    cudaFuncSetAttribute(wgemm_kernel<1, 128>, cudaFuncAttributeMaxDynamicSharedMemorySize, SMEM_BYTES);
    cudaFuncSetAttribute(wgemm_kernel<2, 128>, cudaFuncAttributeMaxDynamicSharedMemorySize, SMEM_BYTES);
    cudaFuncSetAttribute(wgemm_kernel<3, 512>, cudaFuncAttributeMaxDynamicSharedMemorySize, SMEM_BYTES);

    // 0. LN1: x -> g_xn + g_xnh
    ln_kernel<<<(N + 7) / 8, 256>>>(x, ln1_g, ln1_b, N);
    // 1. fold relation matrices into WbigTh/bbig (transposed, fp16)
    prep_w_kernel<<<(Dm * 640 + 255) / 256, 256>>>(kqv_w, kqv_b, a_f, m_f, p_f,
                                                   a_g, m_g, p_g);
    // 2. transpose + convert remaining weights
    prep2_kernel<<<(147456 + 255) / 256, 256>>>(out_w, w1, w2);
    // 3. fused projection GEMM: qh + interleaved kv (direct epilogue)
    wgemm_kernel<0, 128><<<dim3(mtiles, 5), 256, SMEM_BYTES>>>(
        nullptr, nullptr, nullptr, nullptr, nullptr, nullptr, N);
    // 4-7. CSR build by dst
    zero_count_kernel<<<(N + 255) / 256, 256>>>(N);
    count_kernel<<<(2 * E + 255) / 256, 256>>>(ef, eg, E);
    scan_kernel<<<1, 1024>>>(N);
    scatter_kernel<<<(2 * E + 255) / 256, 256>>>(ef, eg, E);
    // 8. fused softmax + aggregation + gelu
    agg_kernel<<<(N + 7) / 8, 256>>>(N);
    // 9. out projection + skip-mix + residual + FUSED LN2 -> g_x1, g_xn2h
    wgemm_kernel<1, 128><<<dim3(mtiles, 1), 256, SMEM_BYTES>>>(
        out_b, x, skip, ln2_g, ln2_b, nullptr, N);
    // 10. FFN up + gelu -> g_hidh (direct epilogue)
    wgemm_kernel<2, 128><<<dim3(mtiles, 4), 256, SMEM_BYTES>>>(
        b1, nullptr, nullptr, nullptr, nullptr, nullptr, N);
    // 11. FFN down + residual -> out (direct epilogue)
    wgemm_kernel<3, 512><<<dim3(mtiles, 1), 256, SMEM_BYTES>>>(
        b2, nullptr, nullptr, nullptr, nullptr, out, N);
}

// round 14
// speedup vs baseline: 1.0416x; 1.0258x over previous
#include <cuda_runtime.h>
#include <cuda_fp16.h>
#include <math.h>
#include <stdint.h>
#include <mma.h>

using namespace nvcuda;

// ---------------- problem-size constants (fixed dataset) ----------------
#define NMAX   50000
#define EMAX   300000
#define Dm     128
#define Hh     8
#define DHd    16

// ---------------- scratch (static device memory; no allocations) --------
__device__ __half g_xnh [NMAX * Dm];       // LN1 output, fp16
__device__ __half g_qh  [NMAX * Dm];       // q, fp16
// g_kv layout per node (512 halves): [f-block 256][g-block 256].
// Within a block, group q (q=0..31) owns halves [q*8, q*8+8):
//   [0:4) = k cols q*4..q*4+3,  [4:8) = v cols q*4..q*4+3.
__device__ __half g_kv  [NMAX * 512];
__device__ __half g_gacth[NMAX * Dm];
__device__ float  g_x1  [NMAX * Dm];
__device__ __half g_xn2h[NMAX * Dm];
__device__ __half g_hidh[NMAX * 4 * Dm];
__device__ __half g_WbigTh[640 * Dm];      // [n][k] fp16
__device__ __half g_outwTh[Dm * Dm];       // [n][k]
__device__ __half g_w1Th  [512 * Dm];      // [n][k]
__device__ __half g_w2Th  [Dm * 512];      // [n][k]
__device__ float  g_bbig [640];
__device__ int    g_count [NMAX];
__device__ int    g_offs  [NMAX + 1];
__device__ int    g_cursor[NMAX];
__device__ int    g_entries[2 * EMAX];

__device__ __forceinline__ float gelu_exact(float v) {
    return v * 0.5f * (1.0f + erff(v * 0.70710678118654752440f));
}

__device__ __forceinline__ uint32_t cvta_s(const void* p) {
    uint32_t a;
    asm("{ .reg .u64 t; cvta.to.shared.u64 t, %1; cvt.u32.u64 %0, t; }"
        : "=r"(a) : "l"(p));
    return a;
}

// ---------------- LayerNorm (LN1): one warp per row -> fp16 -------------
__global__ void ln_kernel(const float* __restrict__ xin,
                          const float* __restrict__ g,
                          const float* __restrict__ b, int N)
{
    int warp = (blockIdx.x * blockDim.x + threadIdx.x) >> 5;
    int lane = threadIdx.x & 31;
    if (warp >= N) return;
    float4 v = *reinterpret_cast<const float4*>(xin + (size_t)warp * Dm + lane * 4);
    float s = v.x + v.y + v.z + v.w;
    #pragma unroll
    for (int o = 16; o; o >>= 1) s += __shfl_xor_sync(0xffffffffu, s, o);
    float mu = s * (1.0f / 128.0f);
    float dx = v.x - mu, dy = v.y - mu, dz = v.z - mu, dw = v.w - mu;
    float s2 = dx * dx + dy * dy + dz * dz + dw * dw;
    #pragma unroll
    for (int o = 16; o; o >>= 1) s2 += __shfl_xor_sync(0xffffffffu, s2, o);
    float r = rsqrtf(s2 * (1.0f / 128.0f) + 1e-5f);
    float4 gg = *reinterpret_cast<const float4*>(g + lane * 4);
    float4 bb = *reinterpret_cast<const float4*>(b + lane * 4);
    __half2 h0 = __floats2half2_rn(dx * r * gg.x + bb.x, dy * r * gg.y + bb.y);
    __half2 h1 = __floats2half2_rn(dz * r * gg.z + bb.z, dw * r * gg.w + bb.w);
    __half2* dst = reinterpret_cast<__half2*>(g_xnh + (size_t)warp * Dm + lane * 4);
    dst[0] = h0; dst[1] = h1;
}

// ---------- fold per-head relation matrices into projection weights ------
__global__ void prep_w_kernel(const float* __restrict__ kqv_w,
                              const float* __restrict__ kqv_b,
                              const float* __restrict__ a_f,
                              const float* __restrict__ m_f,
                              const float* __restrict__ p_f,
                              const float* __restrict__ a_g,
                              const float* __restrict__ m_g,
                              const float* __restrict__ p_g)
{
    int idx = blockIdx.x * blockDim.x + threadIdx.x;
    if (idx >= Dm * 640) return;
    int n = idx % 640;
    int k = idx / 640;
    float val;
    if (n < 128) {
        val = kqv_w[k * 384 + 128 + n];         // q block
        if (k == 0) g_bbig[n] = kqv_b[128 + n];
    } else {
        int gsel = (n - 128) >> 7;              // 0:kf 1:vf 2:kg 3:vg
        int c = (n - 128) & 127;
        int h = c >> 4, f = c & 15;
        const float* mat; int srcoff; float scale = 1.0f;
        if      (gsel == 0) { mat = a_f; srcoff = 0;   scale = p_f[h] * 0.25f; }
        else if (gsel == 1) { mat = m_f; srcoff = 256; }
        else if (gsel == 2) { mat = a_g; srcoff = 0;   scale = p_g[h] * 0.25f; }
        else                { mat = m_g; srcoff = 256; }
        float s = 0.0f, bs = 0.0f;
        #pragma unroll
        for (int d = 0; d < 16; d++) {
            float w = mat[h * 256 + d * 16 + f];
            s  += kqv_w[k * 384 + srcoff + h * 16 + d] * w;
            bs += kqv_b[srcoff + h * 16 + d] * w;
        }
        val = s * scale;
        if (k == 0) g_bbig[n] = bs * scale;
    }
    g_WbigTh[n * Dm + k] = __float2half_rn(val);
}

// ---------- transpose + fp16-round the other weights --------------------
__global__ void prep2_kernel(const float* __restrict__ out_w,
                             const float* __restrict__ w1,
                             const float* __restrict__ w2)
{
    int idx = blockIdx.x * blockDim.x + threadIdx.x;
    if (idx < 128 * 128) {
        int n = idx >> 7, k = idx & 127;
        g_outwTh[n * 128 + k] = __float2half_rn(out_w[k * 128 + n]);
    }
    idx -= 128 * 128;
    if (idx >= 0 && idx < 512 * 128) {
        int n = idx >> 7, k = idx & 127;
        g_w1Th[n * 128 + k] = __float2half_rn(w1[k * 512 + n]);
    }
    idx -= 512 * 128;
    if (idx >= 0 && idx < 128 * 512) {
        int n = idx >> 9, k = idx & 511;
        g_w2Th[n * 512 + k] = __float2half_rn(w2[k * 128 + n]);
    }
}

// ---------------- CSR build: count / scan / scatter ---------------------
__global__ void zero_count_kernel(int N)
{
    int i = blockIdx.x * blockDim.x + threadIdx.x;
    if (i < N) g_count[i] = 0;
}

__global__ void count_kernel(const int* __restrict__ ef,
                             const int* __restrict__ eg, int E)
{
    int i = blockIdx.x * blockDim.x + threadIdx.x;
    if (i >= 2 * E) return;
    int dst = (i < E) ? ef[E + i] : eg[E + (i - E)];
    atomicAdd(&g_count[dst], 1);
}

__global__ void scan_kernel(int N)
{
    __shared__ int sm[1024];
    int t = threadIdx.x;
    int chunk = (N + 1023) >> 10;
    int b0 = t * chunk;
    int b1 = min(b0 + chunk, N);
    int s = 0;
    for (int i = b0; i < b1; i++) s += g_count[i];
    sm[t] = s;
    __syncthreads();
    for (int off = 1; off < 1024; off <<= 1) {
        int v = (t >= off) ? sm[t - off] : 0;
        __syncthreads();
        sm[t] += v;
        __syncthreads();
    }
    int run = sm[t] - s;    // exclusive prefix
    for (int i = b0; i < b1; i++) {
        g_offs[i] = run;
        g_cursor[i] = run;
        run += g_count[i];
    }
    if (t == 1023) g_offs[N] = sm[1023];
}

__global__ void scatter_kernel(const int* __restrict__ ef,
                               const int* __restrict__ eg, int E)
{
    int i = blockIdx.x * blockDim.x + threadIdx.x;
    if (i >= 2 * E) return;
    int src, dst, tbit;
    if (i < E) { src = ef[i];       dst = ef[E + i];       tbit = 0; }
    else       { int j = i - E; src = eg[j]; dst = eg[E + j]; tbit = 1 << 17; }
    int pos = atomicAdd(&g_cursor[dst], 1);
    g_entries[pos] = src | tbit;
}

// ------------- fused segment-softmax + aggregation + GELU ---------------
__global__ void agg_kernel(int N)
{
    int warp = (blockIdx.x * blockDim.x + threadIdx.x) >> 5;
    int lane = threadIdx.x & 31;
    if (warp >= N) return;
    uint2 qr = *reinterpret_cast<const uint2*>(g_qh + (size_t)warp * Dm + lane * 4);
    float2 qa = __half22float2(*reinterpret_cast<__half2*>(&qr.x));
    float2 qb = __half22float2(*reinterpret_cast<__half2*>(&qr.y));
    float4 q4 = make_float4(qa.x, qa.y, qb.x, qb.y);
    float4 acc = make_float4(0.f, 0.f, 0.f, 0.f);
    float denom = 0.0f;
    int beg = g_offs[warp], end = g_offs[warp + 1];
    int j = beg;
    int loff = lane * 8;
    for (; j + 4 <= end; j += 4) {
        uint4 r[4];
        #pragma unroll
        for (int u = 0; u < 4; u++) {
            int e = g_entries[j + u];
            const __half* p = g_kv + ((size_t)(e & 0x1FFFF) << 9)
                                   + ((e >> 9) & 256) + loff;
            r[u] = *reinterpret_cast<const uint4*>(p);
        }
        float ps[4];
        #pragma unroll
        for (int u = 0; u < 4; u++) {
            float2 ka = __half22float2(*reinterpret_cast<__half2*>(&r[u].x));
            float2 kb = __half22float2(*reinterpret_cast<__half2*>(&r[u].y));
            ps[u] = q4.x * ka.x + q4.y * ka.y + q4.z * kb.x + q4.w * kb.y;
        }
        #pragma unroll
        for (int u = 0; u < 4; u++) {
            ps[u] += __shfl_xor_sync(0xffffffffu, ps[u], 1);
            ps[u] += __shfl_xor_sync(0xffffffffu, ps[u], 2);
        }
        #pragma unroll
        for (int u = 0; u < 4; u++) {
            float w = __expf(ps[u]);
            denom += w;
            float2 va = __half22float2(*reinterpret_cast<__half2*>(&r[u].z));
            float2 vb = __half22float2(*reinterpret_cast<__half2*>(&r[u].w));
            acc.x += w * va.x; acc.y += w * va.y;
            acc.z += w * vb.x; acc.w += w * vb.y;
        }
    }
    for (; j < end; j++) {
        int e = g_entries[j];
        const __half* p = g_kv + ((size_t)(e & 0x1FFFF) << 9)
                               + ((e >> 9) & 256) + loff;
        uint4 r = *reinterpret_cast<const uint4*>(p);
        float2 ka = __half22float2(*reinterpret_cast<__half2*>(&r.x));
        float2 kb = __half22float2(*reinterpret_cast<__half2*>(&r.y));
        float ps = q4.x * ka.x + q4.y * ka.y + q4.z * kb.x + q4.w * kb.y;
        ps += __shfl_xor_sync(0xffffffffu, ps, 1);
        ps += __shfl_xor_sync(0xffffffffu, ps, 2);
        float w = __expf(ps);
        denom += w;
        float2 va = __half22float2(*reinterpret_cast<__half2*>(&r.z));
        float2 vb = __half22float2(*reinterpret_cast<__half2*>(&r.w));
        acc.x += w * va.x; acc.y += w * va.y;
        acc.z += w * vb.x; acc.w += w * vb.y;
    }
    float rd = 1.0f / (denom + 1e-16f);
    __half2 o0 = __floats2half2_rn(gelu_exact(acc.x * rd), gelu_exact(acc.y * rd));
    __half2 o1 = __floats2half2_rn(gelu_exact(acc.z * rd), gelu_exact(acc.w * rd));
    __half2* dst = reinterpret_cast<__half2*>(g_gacth + (size_t)warp * Dm + lane * 4);
    dst[0] = o0; dst[1] = o1;
}

// =========== fp16 wmma GEMM: C = A[M,K] @ Bt[N,K]^T ======================
// 128x128 CTA tile; 256 threads = 8 warps (2Mx4N), warp tile 64x32 =
// 4x2 wmma m16n16k16, fp32 accumulate, 2 CTAs/SM, cp.async staging,
// smem C overlay + coalesced fused epilogues.
// MODE 0: A=g_xnh,  Bt=g_WbigTh -> qh(fp16) / interleaved g_kv  K=128, 5 nt
// MODE 1: A=g_gacth,Bt=g_outwTh -> g_x1 + FUSED LN2 -> g_xn2h  K=128
// MODE 2: A=g_xn2h, Bt=g_w1Th   -> g_hidh = gelu(C+b1) fp16   K=128, 4 nt
// MODE 3: A=g_hidh, Bt=g_w2Th   -> out = g_x1 + C + b2        K=512
#define APADH 136                          // halves per row (stride)
#define CPAD  132                          // floats per row for C overlay
#define SMEM_BYTES (2 * 128 * APADH * 2)   // 69632 bytes

template <int MODE, int K>
__global__ void __launch_bounds__(256, 2)
wgemm_kernel(const float* __restrict__ bias,
             const float* __restrict__ aux,    // MODE1: x
             const float* __restrict__ skip,   // MODE1 only
             const float* __restrict__ lng,    // MODE1: ln2 gamma
             const float* __restrict__ lnb,    // MODE1: ln2 beta
             float* __restrict__ outp,         // MODE3: d_out
             int M)
{
    extern __shared__ char smem[];
    __half* sA = reinterpret_cast<__half*>(smem);
    __half* sB = reinterpret_cast<__half*>(smem) + 128 * APADH;
    float*  sC = reinterpret_cast<float*>(smem);

    int tid = threadIdx.x;
    int wid = tid >> 5;
    int lane = tid & 31;
    int m0 = blockIdx.x * 128;
    int n0 = blockIdx.y * 128;

    int wm = (wid & 1) * 64;             // 2 M groups of 64 rows
    int wn = (wid >> 1) * 32;            // 4 N groups of 32 cols

    const __half* A;
    const __half* Bt;
    if      (MODE == 0) { A = g_xnh;   Bt = g_WbigTh; }
    else if (MODE == 1) { A = g_gacth; Bt = g_outwTh; }
    else if (MODE == 2) { A = g_xn2h;  Bt = g_w1Th;   }
    else                { A = g_hidh;  Bt = g_w2Th;   }

    wmma::fragment<wmma::accumulator, 16, 16, 16, float> acc[4][2];
    #pragma unroll
    for (int i = 0; i < 4; i++)
        #pragma unroll
        for (int j = 0; j < 2; j++)
            wmma::fill_fragment(acc[i][j], 0.0f);

    for (int kc = 0; kc < K; kc += 128) {
        // ---- cp.async staging: 16B per copy, zero-fill beyond M ----
        #pragma unroll
        for (int i = tid; i < 128 * 16; i += 256) {
            int row = i >> 4, g8 = i & 15;
            int gm = m0 + row;
            uint32_t da = cvta_s(&sA[row * APADH + g8 * 8]);
            const __half* srcA = A + (size_t)gm * K + kc + g8 * 8;
            int szA = (gm < M) ? 16 : 0;
            asm volatile("cp.async.cg.shared.global [%0], [%1], 16, %2;"
                         :: "r"(da), "l"(srcA), "r"(szA));
            uint32_t db = cvta_s(&sB[row * APADH + g8 * 8]);
            const __half* srcB = Bt + (size_t)(n0 + row) * K + kc + g8 * 8;
            asm volatile("cp.async.cg.shared.global [%0], [%1], 16;"
                         :: "r"(db), "l"(srcB));
        }
        asm volatile("cp.async.commit_group;");
        asm volatile("cp.async.wait_group 0;" ::: "memory");
        __syncthreads();

        // ---- 8 k-steps of wmma m16n16k16 (B outer, A streamed) ----
        #pragma unroll
        for (int ks = 0; ks < 8; ks++) {
            wmma::fragment<wmma::matrix_b, 16, 16, 16, __half, wmma::col_major> bf[2];
            #pragma unroll
            for (int j = 0; j < 2; j++)
                wmma::load_matrix_sync(bf[j], &sB[(wn + j * 16) * APADH + ks * 16], APADH);
            #pragma unroll
            for (int i = 0; i < 4; i++) {
                wmma::fragment<wmma::matrix_a, 16, 16, 16, __half, wmma::row_major> af;
                wmma::load_matrix_sync(af, &sA[(wm + i * 16) * APADH + ks * 16], APADH);
                wmma::mma_sync(acc[i][0], af, bf[0], acc[i][0]);
                wmma::mma_sync(acc[i][1], af, bf[1], acc[i][1]);
            }
        }
        __syncthreads();
    }

    // ---- dump C tile into float overlay ----
    #pragma unroll
    for (int i = 0; i < 4; i++)
        #pragma unroll
        for (int j = 0; j < 2; j++)
            wmma::store_matrix_sync(&sC[(wm + i * 16) * CPAD + wn + j * 16],
                                    acc[i][j], CPAD, wmma::mem_row_major);
    __syncthreads();

    if (MODE == 1) {
        // fused: x1 = x + sig*(C+b) + (1-sig)*xnh ; then LN2 -> g_xn2h
        float sig = 1.0f / (1.0f + __expf(-skip[0]));
        float om = 1.0f - sig;
        float4 bb  = *reinterpret_cast<const float4*>(bias + lane * 4);
        float4 gg  = *reinterpret_cast<const float4*>(lng + lane * 4);
        float4 be  = *reinterpret_cast<const float4*>(lnb + lane * 4);
        for (int r = wid; r < 128; r += 8) {
            int gm = m0 + r;
            if (gm >= M) continue;
            float4 v = *reinterpret_cast<float4*>(&sC[r * CPAD + lane * 4]);
            float4 xv = *reinterpret_cast<const float4*>(aux + (size_t)gm * Dm + lane * 4);
            uint2 xr = *reinterpret_cast<const uint2*>(g_xnh + (size_t)gm * Dm + lane * 4);
            float2 xa = __half22float2(*reinterpret_cast<__half2*>(&xr.x));
            float2 xb = __half22float2(*reinterpret_cast<__half2*>(&xr.y));
            v.x = xv.x + sig * (v.x + bb.x) + om * xa.x;
            v.y = xv.y + sig * (v.y + bb.y) + om * xa.y;
            v.z = xv.z + sig * (v.z + bb.z) + om * xb.x;
            v.w = xv.w + sig * (v.w + bb.w) + om * xb.y;
            *reinterpret_cast<float4*>(g_x1 + (size_t)gm * Dm + lane * 4) = v;
            float s = v.x + v.y + v.z + v.w;
            #pragma unroll
            for (int o = 16; o; o >>= 1) s += __shfl_xor_sync(0xffffffffu, s, o);
            float mu = s * (1.0f / 128.0f);
            float dx = v.x - mu, dy = v.y - mu, dz = v.z - mu, dw = v.w - mu;
            float s2 = dx * dx + dy * dy + dz * dz + dw * dw;
            #pragma unroll
            for (int o = 16; o; o >>= 1) s2 += __shfl_xor_sync(0xffffffffu, s2, o);
            float rr = rsqrtf(s2 * (1.0f / 128.0f) + 1e-5f);
            __half2 h0 = __floats2half2_rn(dx * rr * gg.x + be.x, dy * rr * gg.y + be.y);
            __half2 h1 = __floats2half2_rn(dz * rr * gg.z + be.z, dw * rr * gg.w + be.w);
            __half2* dst = reinterpret_cast<__half2*>(g_xn2h + (size_t)gm * Dm + lane * 4);
            dst[0] = h0; dst[1] = h1;
        }
        return;
    }

    #pragma unroll
    for (int i = tid; i < 128 * 32; i += 256) {
        int row = i >> 5, q = i & 31;
        int gm = m0 + row;
        if (gm >= M) continue;
        float4 v = *reinterpret_cast<float4*>(&sC[row * CPAD + q * 4]);
        int gn = n0 + q * 4;
        if (MODE == 0) {
            float4 bb = *reinterpret_cast<const float4*>(g_bbig + gn);
            v.x += bb.x; v.y += bb.y; v.z += bb.z; v.w += bb.w;
            __half2 h0 = __floats2half2_rn(v.x, v.y);
            __half2 h1 = __floats2half2_rn(v.z, v.w);
            if (blockIdx.y == 0) {
                __half2* dst = reinterpret_cast<__half2*>(
                    g_qh + (size_t)gm * Dm + q * 4);
                dst[0] = h0; dst[1] = h1;
            } else {
                int type = blockIdx.y - 1;      // kf,vf,kg,vg
                int tb = (type >> 1) * 256;
                int koff = (type & 1) * 4;
                __half* base = g_kv + ((size_t)gm << 9) + tb + q * 8 + koff;
                *reinterpret_cast<__half2*>(base) = h0;
                *reinterpret_cast<__half2*>(base + 2) = h1;
            }
        } else if (MODE == 2) {
            float4 bb = *reinterpret_cast<const float4*>(bias + gn);
            __half2 h0 = __floats2half2_rn(gelu_exact(v.x + bb.x), gelu_exact(v.y + bb.y));
            __half2 h1 = __floats2half2_rn(gelu_exact(v.z + bb.z), gelu_exact(v.w + bb.w));
            __half2* dst = reinterpret_cast<__half2*>(g_hidh + (size_t)gm * 512 + gn);
            dst[0] = h0; dst[1] = h1;
        } else {
            float4 bb = *reinterpret_cast<const float4*>(bias + gn);
            float4 x1 = *reinterpret_cast<const float4*>(g_x1 + (size_t)gm * Dm + gn);
            v.x = x1.x + v.x + bb.x;
            v.y = x1.y + v.y + bb.y;
            v.z = x1.z + v.z + bb.z;
            v.w = x1.w + v.w + bb.w;
            *reinterpret_cast<float4*>(outp + (size_t)gm * Dm + gn) = v;
        }
    }
}

// ------------------------------- launch ---------------------------------
extern "C" void kernel_launch(void* const* d_in, const int* in_sizes, int n_in,
                              void* d_out, int out_size)
{
    const float* x      = (const float*)d_in[0];
    const int*   ef     = (const int*)  d_in[1];
    const int*   eg     = (const int*)  d_in[2];
    const float* kqv_w  = (const float*)d_in[3];
    const float* kqv_b  = (const float*)d_in[4];
    const float* a_f    = (const float*)d_in[5];
    const float* m_f    = (const float*)d_in[6];
    const float* p_f    = (const float*)d_in[7];
    const float* a_g    = (const float*)d_in[8];
    const float* m_g    = (const float*)d_in[9];
    const float* p_g    = (const float*)d_in[10];
    const float* out_w  = (const float*)d_in[11];
    const float* out_b  = (const float*)d_in[12];
    const float* skip   = (const float*)d_in[13];
    const float* ln1_g  = (const float*)d_in[14];
    const float* ln1_b  = (const float*)d_in[15];
    const float* ln2_g  = (const float*)d_in[16];
    const float* ln2_b  = (const float*)d_in[17];
    const float* w1     = (const float*)d_in[18];
    const float* b1     = (const float*)d_in[19];
    const float* w2     = (const float*)d_in[20];
    const float* b2     = (const float*)d_in[21];
    float* out = (float*)d_out;

    int N = in_sizes[0] / Dm;
    int E = in_sizes[1] / 2;
    if (N > NMAX) N = NMAX;
    if (E > EMAX) E = EMAX;

    int mtiles = (N + 127) / 128;

    cudaFuncSetAttribute(wgemm_kernel<0, 128>, cudaFuncAttributeMaxDynamicSharedMemorySize, SMEM_BYTES);
    cudaFuncSetAttribute(wgemm_kernel<1, 128>, cudaFuncAttributeMaxDynamicSharedMemorySize, SMEM_BYTES);
    cudaFuncSetAttribute(wgemm_kernel<2, 128>, cudaFuncAttributeMaxDynamicSharedMemorySize, SMEM_BYTES);
    cudaFuncSetAttribute(wgemm_kernel<3, 512>, cudaFuncAttributeMaxDynamicSharedMemorySize, SMEM_BYTES);

    // 0. LN1: x -> g_xnh
    ln_kernel<<<(N + 7) / 8, 256>>>(x, ln1_g, ln1_b, N);
    // 1. fold relation matrices into WbigTh/bbig (transposed, fp16)
    prep_w_kernel<<<(Dm * 640 + 255) / 256, 256>>>(kqv_w, kqv_b, a_f, m_f, p_f,
                                                   a_g, m_g, p_g);
    // 2. transpose + convert remaining weights
    prep2_kernel<<<(147456 + 255) / 256, 256>>>(out_w, w1, w2);
    // 3. fused projection GEMM: qh + interleaved kv
    wgemm_kernel<0, 128><<<dim3(mtiles, 5), 256, SMEM_BYTES>>>(
        nullptr, nullptr, nullptr, nullptr, nullptr, nullptr, N);
    // 4-7. CSR build by dst
    zero_count_kernel<<<(N + 255) / 256, 256>>>(N);
    count_kernel<<<(2 * E + 255) / 256, 256>>>(ef, eg, E);
    scan_kernel<<<1, 1024>>>(N);
    scatter_kernel<<<(2 * E + 255) / 256, 256>>>(ef, eg, E);
    // 8. fused softmax + aggregation + gelu
    agg_kernel<<<(N + 7) / 8, 256>>>(N);
    // 9. out projection + skip-mix + residual + FUSED LN2 -> g_x1, g_xn2h
    wgemm_kernel<1, 128><<<dim3(mtiles, 1), 256, SMEM_BYTES>>>(
        out_b, x, skip, ln2_g, ln2_b, nullptr, N);
    // 10. FFN up + gelu -> g_hidh (fp16)
    wgemm_kernel<2, 128><<<dim3(mtiles, 4), 256, SMEM_BYTES>>>(
        b1, nullptr, nullptr, nullptr, nullptr, nullptr, N);
    // 11. FFN down + residual -> out
    wgemm_kernel<3, 512><<<dim3(mtiles, 1), 256, SMEM_BYTES>>>(
        b2, nullptr, nullptr, nullptr, nullptr, out, N);
}

// round 15
// speedup vs baseline: 1.0695x; 1.0268x over previous
#include <cuda_runtime.h>
#include <cuda_fp16.h>
#include <math.h>
#include <stdint.h>
#include <mma.h>

using namespace nvcuda;

// ---------------- problem-size constants (fixed dataset) ----------------
#define NMAX   50000
#define EMAX   300000
#define Dm     128
#define Hh     8
#define DHd    16

// ---------------- scratch (static device memory; no allocations) --------
__device__ __half g_xnh [NMAX * Dm];       // LN1 output, fp16
__device__ __half g_qh  [NMAX * Dm];       // q, fp16
// g_kv layout per node (512 halves): [f-block 256][g-block 256].
// Within a block, group q (q=0..31) owns halves [q*8, q*8+8):
//   [0:4) = k cols q*4..q*4+3,  [4:8) = v cols q*4..q*4+3.
__device__ __half g_kv  [NMAX * 512];
__device__ __half g_gacth[NMAX * Dm];
__device__ float  g_x1  [NMAX * Dm];
__device__ __half g_xn2h[NMAX * Dm];
__device__ __half g_hidh[NMAX * 4 * Dm];
__device__ __half g_WbigTh[640 * Dm];      // [n][k] fp16
__device__ __half g_outwTh[Dm * Dm];       // [n][k]
__device__ __half g_w1Th  [512 * Dm];      // [n][k]
__device__ __half g_w2Th  [Dm * 512];      // [n][k]
__device__ float  g_bbig [640];
__device__ int    g_count [NMAX];
__device__ int    g_offs  [NMAX + 1];
__device__ int    g_cursor[NMAX];
__device__ int    g_entries[2 * EMAX];

__device__ __forceinline__ float gelu_exact(float v) {
    return v * 0.5f * (1.0f + erff(v * 0.70710678118654752440f));
}

__device__ __forceinline__ uint32_t cvta_s(const void* p) {
    uint32_t a;
    asm("{ .reg .u64 t; cvta.to.shared.u64 t, %1; cvt.u32.u64 %0, t; }"
        : "=r"(a) : "l"(p));
    return a;
}

// ====== fused setup: LN1 | prep_w | prep2 | zero_count (grid-split) ======
__global__ void setup_kernel(const float* __restrict__ x,
                             const float* __restrict__ ln1_g,
                             const float* __restrict__ ln1_b,
                             const float* __restrict__ kqv_w,
                             const float* __restrict__ kqv_b,
                             const float* __restrict__ a_f,
                             const float* __restrict__ m_f,
                             const float* __restrict__ p_f,
                             const float* __restrict__ a_g,
                             const float* __restrict__ m_g,
                             const float* __restrict__ p_g,
                             const float* __restrict__ out_w,
                             const float* __restrict__ w1,
                             const float* __restrict__ w2,
                             int N, int lnb)
{
    int b = blockIdx.x;
    if (b < lnb) {
        // ---- LN1: one warp per row -> g_xnh ----
        int warp = ((b * 256) + threadIdx.x) >> 5;
        int lane = threadIdx.x & 31;
        if (warp >= N) return;
        float4 v = *reinterpret_cast<const float4*>(x + (size_t)warp * Dm + lane * 4);
        float s = v.x + v.y + v.z + v.w;
        #pragma unroll
        for (int o = 16; o; o >>= 1) s += __shfl_xor_sync(0xffffffffu, s, o);
        float mu = s * (1.0f / 128.0f);
        float dx = v.x - mu, dy = v.y - mu, dz = v.z - mu, dw = v.w - mu;
        float s2 = dx * dx + dy * dy + dz * dz + dw * dw;
        #pragma unroll
        for (int o = 16; o; o >>= 1) s2 += __shfl_xor_sync(0xffffffffu, s2, o);
        float r = rsqrtf(s2 * (1.0f / 128.0f) + 1e-5f);
        float4 gg = *reinterpret_cast<const float4*>(ln1_g + lane * 4);
        float4 bb = *reinterpret_cast<const float4*>(ln1_b + lane * 4);
        __half2 h0 = __floats2half2_rn(dx * r * gg.x + bb.x, dy * r * gg.y + bb.y);
        __half2 h1 = __floats2half2_rn(dz * r * gg.z + bb.z, dw * r * gg.w + bb.w);
        __half2* dst = reinterpret_cast<__half2*>(g_xnh + (size_t)warp * Dm + lane * 4);
        dst[0] = h0; dst[1] = h1;
        return;
    }
    b -= lnb;
    if (b < 320) {
        // ---- prep_w: fold relation mats into WbigTh/bbig ----
        int idx = b * 256 + threadIdx.x;
        if (idx >= Dm * 640) return;
        int n = idx % 640;
        int k = idx / 640;
        float val;
        if (n < 128) {
            val = kqv_w[k * 384 + 128 + n];
            if (k == 0) g_bbig[n] = kqv_b[128 + n];
        } else {
            int gsel = (n - 128) >> 7;
            int c = (n - 128) & 127;
            int h = c >> 4, f = c & 15;
            const float* mat; int srcoff; float scale = 1.0f;
            if      (gsel == 0) { mat = a_f; srcoff = 0;   scale = p_f[h] * 0.25f; }
            else if (gsel == 1) { mat = m_f; srcoff = 256; }
            else if (gsel == 2) { mat = a_g; srcoff = 0;   scale = p_g[h] * 0.25f; }
            else                { mat = m_g; srcoff = 256; }
            float s = 0.0f, bs = 0.0f;
            #pragma unroll
            for (int d = 0; d < 16; d++) {
                float w = mat[h * 256 + d * 16 + f];
                s  += kqv_w[k * 384 + srcoff + h * 16 + d] * w;
                bs += kqv_b[srcoff + h * 16 + d] * w;
            }
            val = s * scale;
            if (k == 0) g_bbig[n] = bs * scale;
        }
        g_WbigTh[n * Dm + k] = __float2half_rn(val);
        return;
    }
    b -= 320;
    if (b < 576) {
        // ---- prep2: transpose + fp16 other weights ----
        int idx = b * 256 + threadIdx.x;
        if (idx < 128 * 128) {
            int n = idx >> 7, k = idx & 127;
            g_outwTh[n * 128 + k] = __float2half_rn(out_w[k * 128 + n]);
        }
        idx -= 128 * 128;
        if (idx >= 0 && idx < 512 * 128) {
            int n = idx >> 7, k = idx & 127;
            g_w1Th[n * 128 + k] = __float2half_rn(w1[k * 512 + n]);
        }
        idx -= 512 * 128;
        if (idx >= 0 && idx < 128 * 512) {
            int n = idx >> 9, k = idx & 511;
            g_w2Th[n * 512 + k] = __float2half_rn(w2[k * 128 + n]);
        }
        return;
    }
    b -= 576;
    {
        int i = b * 256 + threadIdx.x;
        if (i < N) g_count[i] = 0;
    }
}

// ---------------- CSR build: count / scan / scatter ---------------------
__global__ void count_kernel(const int* __restrict__ ef,
                             const int* __restrict__ eg, int E)
{
    int i = blockIdx.x * blockDim.x + threadIdx.x;
    if (i >= 2 * E) return;
    int dst = (i < E) ? ef[E + i] : eg[E + (i - E)];
    atomicAdd(&g_count[dst], 1);
}

__global__ void scan_kernel(int N)
{
    __shared__ int sm[1024];
    int t = threadIdx.x;
    int chunk = (N + 1023) >> 10;
    int b0 = t * chunk;
    int b1 = min(b0 + chunk, N);
    int s = 0;
    for (int i = b0; i < b1; i++) s += g_count[i];
    sm[t] = s;
    __syncthreads();
    for (int off = 1; off < 1024; off <<= 1) {
        int v = (t >= off) ? sm[t - off] : 0;
        __syncthreads();
        sm[t] += v;
        __syncthreads();
    }
    int run = sm[t] - s;    // exclusive prefix
    for (int i = b0; i < b1; i++) {
        g_offs[i] = run;
        g_cursor[i] = run;
        run += g_count[i];
    }
    if (t == 1023) g_offs[N] = sm[1023];
}

__global__ void scatter_kernel(const int* __restrict__ ef,
                               const int* __restrict__ eg, int E)
{
    int i = blockIdx.x * blockDim.x + threadIdx.x;
    if (i >= 2 * E) return;
    int src, dst, tbit;
    if (i < E) { src = ef[i];       dst = ef[E + i];       tbit = 0; }
    else       { int j = i - E; src = eg[j]; dst = eg[E + j]; tbit = 1 << 17; }
    int pos = atomicAdd(&g_cursor[dst], 1);
    g_entries[pos] = src | tbit;
}

// ------------- fused segment-softmax + aggregation + GELU ---------------
// One warp/node. 8-deep gather pipeline: 8 independent uint4 loads in
// flight per warp before any consumption (latency-bound fix).
__global__ void agg_kernel(int N)
{
    int warp = (blockIdx.x * blockDim.x + threadIdx.x) >> 5;
    int lane = threadIdx.x & 31;
    if (warp >= N) return;
    uint2 qr = *reinterpret_cast<const uint2*>(g_qh + (size_t)warp * Dm + lane * 4);
    float2 qa = __half22float2(*reinterpret_cast<__half2*>(&qr.x));
    float2 qb = __half22float2(*reinterpret_cast<__half2*>(&qr.y));
    float4 q4 = make_float4(qa.x, qa.y, qb.x, qb.y);
    float4 acc = make_float4(0.f, 0.f, 0.f, 0.f);
    float denom = 0.0f;
    int beg = g_offs[warp], end = g_offs[warp + 1];
    int j = beg;
    int loff = lane * 8;
    for (; j + 8 <= end; j += 8) {
        int e[8];
        #pragma unroll
        for (int u = 0; u < 8; u++) e[u] = g_entries[j + u];
        uint4 r[8];
        #pragma unroll
        for (int u = 0; u < 8; u++) {
            const __half* p = g_kv + ((size_t)(e[u] & 0x1FFFF) << 9)
                                   + ((e[u] >> 9) & 256) + loff;
            r[u] = *reinterpret_cast<const uint4*>(p);
        }
        float ps[8];
        #pragma unroll
        for (int u = 0; u < 8; u++) {
            float2 ka = __half22float2(*reinterpret_cast<__half2*>(&r[u].x));
            float2 kb = __half22float2(*reinterpret_cast<__half2*>(&r[u].y));
            ps[u] = q4.x * ka.x + q4.y * ka.y + q4.z * kb.x + q4.w * kb.y;
        }
        #pragma unroll
        for (int u = 0; u < 8; u++)
            ps[u] += __shfl_xor_sync(0xffffffffu, ps[u], 1);
        #pragma unroll
        for (int u = 0; u < 8; u++)
            ps[u] += __shfl_xor_sync(0xffffffffu, ps[u], 2);
        #pragma unroll
        for (int u = 0; u < 8; u++) {
            float w = __expf(ps[u]);
            denom += w;
            float2 va = __half22float2(*reinterpret_cast<__half2*>(&r[u].z));
            float2 vb = __half22float2(*reinterpret_cast<__half2*>(&r[u].w));
            acc.x += w * va.x; acc.y += w * va.y;
            acc.z += w * vb.x; acc.w += w * vb.y;
        }
    }
    for (; j + 4 <= end; j += 4) {
        uint4 r[4];
        #pragma unroll
        for (int u = 0; u < 4; u++) {
            int e = g_entries[j + u];
            const __half* p = g_kv + ((size_t)(e & 0x1FFFF) << 9)
                                   + ((e >> 9) & 256) + loff;
            r[u] = *reinterpret_cast<const uint4*>(p);
        }
        float ps[4];
        #pragma unroll
        for (int u = 0; u < 4; u++) {
            float2 ka = __half22float2(*reinterpret_cast<__half2*>(&r[u].x));
            float2 kb = __half22float2(*reinterpret_cast<__half2*>(&r[u].y));
            ps[u] = q4.x * ka.x + q4.y * ka.y + q4.z * kb.x + q4.w * kb.y;
        }
        #pragma unroll
        for (int u = 0; u < 4; u++) {
            ps[u] += __shfl_xor_sync(0xffffffffu, ps[u], 1);
            ps[u] += __shfl_xor_sync(0xffffffffu, ps[u], 2);
        }
        #pragma unroll
        for (int u = 0; u < 4; u++) {
            float w = __expf(ps[u]);
            denom += w;
            float2 va = __half22float2(*reinterpret_cast<__half2*>(&r[u].z));
            float2 vb = __half22float2(*reinterpret_cast<__half2*>(&r[u].w));
            acc.x += w * va.x; acc.y += w * va.y;
            acc.z += w * vb.x; acc.w += w * vb.y;
        }
    }
    for (; j < end; j++) {
        int e = g_entries[j];
        const __half* p = g_kv + ((size_t)(e & 0x1FFFF) << 9)
                               + ((e >> 9) & 256) + loff;
        uint4 r = *reinterpret_cast<const uint4*>(p);
        float2 ka = __half22float2(*reinterpret_cast<__half2*>(&r.x));
        float2 kb = __half22float2(*reinterpret_cast<__half2*>(&r.y));
        float ps = q4.x * ka.x + q4.y * ka.y + q4.z * kb.x + q4.w * kb.y;
        ps += __shfl_xor_sync(0xffffffffu, ps, 1);
        ps += __shfl_xor_sync(0xffffffffu, ps, 2);
        float w = __expf(ps);
        denom += w;
        float2 va = __half22float2(*reinterpret_cast<__half2*>(&r.z));
        float2 vb = __half22float2(*reinterpret_cast<__half2*>(&r.w));
        acc.x += w * va.x; acc.y += w * va.y;
        acc.z += w * vb.x; acc.w += w * vb.y;
    }
    float rd = 1.0f / (denom + 1e-16f);
    __half2 o0 = __floats2half2_rn(gelu_exact(acc.x * rd), gelu_exact(acc.y * rd));
    __half2 o1 = __floats2half2_rn(gelu_exact(acc.z * rd), gelu_exact(acc.w * rd));
    __half2* dst = reinterpret_cast<__half2*>(g_gacth + (size_t)warp * Dm + lane * 4);
    dst[0] = o0; dst[1] = o1;
}

// =========== fp16 wmma GEMM: C = A[M,K] @ Bt[N,K]^T ======================
// (round-14 validated structure: 2Mx4N warps, cp.async staging, smem C
// overlay + coalesced fused epilogues, 2 CTAs/SM)
// MODE 0: A=g_xnh,  Bt=g_WbigTh -> qh(fp16) / interleaved g_kv  K=128, 5 nt
// MODE 1: A=g_gacth,Bt=g_outwTh -> g_x1 + FUSED LN2 -> g_xn2h  K=128
// MODE 2: A=g_xn2h, Bt=g_w1Th   -> g_hidh = gelu(C+b1) fp16   K=128, 4 nt
// MODE 3: A=g_hidh, Bt=g_w2Th   -> out = g_x1 + C + b2        K=512
#define APADH 136                          // halves per row (stride)
#define CPAD  132                          // floats per row for C overlay
#define SMEM_BYTES (2 * 128 * APADH * 2)   // 69632 bytes

template <int MODE, int K>
__global__ void __launch_bounds__(256, 2)
wgemm_kernel(const float* __restrict__ bias,
             const float* __restrict__ aux,    // MODE1: x
             const float* __restrict__ skip,   // MODE1 only
             const float* __restrict__ lng,    // MODE1: ln2 gamma
             const float* __restrict__ lnb,    // MODE1: ln2 beta
             float* __restrict__ outp,         // MODE3: d_out
             int M)
{
    extern __shared__ char smem[];
    __half* sA = reinterpret_cast<__half*>(smem);
    __half* sB = reinterpret_cast<__half*>(smem) + 128 * APADH;
    float*  sC = reinterpret_cast<float*>(smem);

    int tid = threadIdx.x;
    int wid = tid >> 5;
    int lane = tid & 31;
    int m0 = blockIdx.x * 128;
    int n0 = blockIdx.y * 128;

    int wm = (wid & 1) * 64;
    int wn = (wid >> 1) * 32;

    const __half* A;
    const __half* Bt;
    if      (MODE == 0) { A = g_xnh;   Bt = g_WbigTh; }
    else if (MODE == 1) { A = g_gacth; Bt = g_outwTh; }
    else if (MODE == 2) { A = g_xn2h;  Bt = g_w1Th;   }
    else                { A = g_hidh;  Bt = g_w2Th;   }

    wmma::fragment<wmma::accumulator, 16, 16, 16, float> acc[4][2];
    #pragma unroll
    for (int i = 0; i < 4; i++)
        #pragma unroll
        for (int j = 0; j < 2; j++)
            wmma::fill_fragment(acc[i][j], 0.0f);

    for (int kc = 0; kc < K; kc += 128) {
        #pragma unroll
        for (int i = tid; i < 128 * 16; i += 256) {
            int row = i >> 4, g8 = i & 15;
            int gm = m0 + row;
            uint32_t da = cvta_s(&sA[row * APADH + g8 * 8]);
            const __half* srcA = A + (size_t)gm * K + kc + g8 * 8;
            int szA = (gm < M) ? 16 : 0;
            asm volatile("cp.async.cg.shared.global [%0], [%1], 16, %2;"
                         :: "r"(da), "l"(srcA), "r"(szA));
            uint32_t db = cvta_s(&sB[row * APADH + g8 * 8]);
            const __half* srcB = Bt + (size_t)(n0 + row) * K + kc + g8 * 8;
            asm volatile("cp.async.cg.shared.global [%0], [%1], 16;"
                         :: "r"(db), "l"(srcB));
        }
        asm volatile("cp.async.commit_group;");
        asm volatile("cp.async.wait_group 0;" ::: "memory");
        __syncthreads();

        #pragma unroll
        for (int ks = 0; ks < 8; ks++) {
            wmma::fragment<wmma::matrix_b, 16, 16, 16, __half, wmma::col_major> bf[2];
            #pragma unroll
            for (int j = 0; j < 2; j++)
                wmma::load_matrix_sync(bf[j], &sB[(wn + j * 16) * APADH + ks * 16], APADH);
            #pragma unroll
            for (int i = 0; i < 4; i++) {
                wmma::fragment<wmma::matrix_a, 16, 16, 16, __half, wmma::row_major> af;
                wmma::load_matrix_sync(af, &sA[(wm + i * 16) * APADH + ks * 16], APADH);
                wmma::mma_sync(acc[i][0], af, bf[0], acc[i][0]);
                wmma::mma_sync(acc[i][1], af, bf[1], acc[i][1]);
            }
        }
        __syncthreads();
    }

    #pragma unroll
    for (int i = 0; i < 4; i++)
        #pragma unroll
        for (int j = 0; j < 2; j++)
            wmma::store_matrix_sync(&sC[(wm + i * 16) * CPAD + wn + j * 16],
                                    acc[i][j], CPAD, wmma::mem_row_major);
    __syncthreads();

    if (MODE == 1) {
        float sig = 1.0f / (1.0f + __expf(-skip[0]));
        float om = 1.0f - sig;
        float4 bb  = *reinterpret_cast<const float4*>(bias + lane * 4);
        float4 gg  = *reinterpret_cast<const float4*>(lng + lane * 4);
        float4 be  = *reinterpret_cast<const float4*>(lnb + lane * 4);
        for (int r = wid; r < 128; r += 8) {
            int gm = m0 + r;
            if (gm >= M) continue;
            float4 v = *reinterpret_cast<float4*>(&sC[r * CPAD + lane * 4]);
            float4 xv = *reinterpret_cast<const float4*>(aux + (size_t)gm * Dm + lane * 4);
            uint2 xr = *reinterpret_cast<const uint2*>(g_xnh + (size_t)gm * Dm + lane * 4);
            float2 xa = __half22float2(*reinterpret_cast<__half2*>(&xr.x));
            float2 xb = __half22float2(*reinterpret_cast<__half2*>(&xr.y));
            v.x = xv.x + sig * (v.x + bb.x) + om * xa.x;
            v.y = xv.y + sig * (v.y + bb.y) + om * xa.y;
            v.z = xv.z + sig * (v.z + bb.z) + om * xb.x;
            v.w = xv.w + sig * (v.w + bb.w) + om * xb.y;
            *reinterpret_cast<float4*>(g_x1 + (size_t)gm * Dm + lane * 4) = v;
            float s = v.x + v.y + v.z + v.w;
            #pragma unroll
            for (int o = 16; o; o >>= 1) s += __shfl_xor_sync(0xffffffffu, s, o);
            float mu = s * (1.0f / 128.0f);
            float dx = v.x - mu, dy = v.y - mu, dz = v.z - mu, dw = v.w - mu;
            float s2 = dx * dx + dy * dy + dz * dz + dw * dw;
            #pragma unroll
            for (int o = 16; o; o >>= 1) s2 += __shfl_xor_sync(0xffffffffu, s2, o);
            float rr = rsqrtf(s2 * (1.0f / 128.0f) + 1e-5f);
            __half2 h0 = __floats2half2_rn(dx * rr * gg.x + be.x, dy * rr * gg.y + be.y);
            __half2 h1 = __floats2half2_rn(dz * rr * gg.z + be.z, dw * rr * gg.w + be.w);
            __half2* dst = reinterpret_cast<__half2*>(g_xn2h + (size_t)gm * Dm + lane * 4);
            dst[0] = h0; dst[1] = h1;
        }
        return;
    }

    #pragma unroll
    for (int i = tid; i < 128 * 32; i += 256) {
        int row = i >> 5, q = i & 31;
        int gm = m0 + row;
        if (gm >= M) continue;
        float4 v = *reinterpret_cast<float4*>(&sC[row * CPAD + q * 4]);
        int gn = n0 + q * 4;
        if (MODE == 0) {
            float4 bb = *reinterpret_cast<const float4*>(g_bbig + gn);
            v.x += bb.x; v.y += bb.y; v.z += bb.z; v.w += bb.w;
            __half2 h0 = __floats2half2_rn(v.x, v.y);
            __half2 h1 = __floats2half2_rn(v.z, v.w);
            if (blockIdx.y == 0) {
                __half2* dst = reinterpret_cast<__half2*>(
                    g_qh + (size_t)gm * Dm + q * 4);
                dst[0] = h0; dst[1] = h1;
            } else {
                int type = blockIdx.y - 1;      // kf,vf,kg,vg
                int tb = (type >> 1) * 256;
                int koff = (type & 1) * 4;
                __half* base = g_kv + ((size_t)gm << 9) + tb + q * 8 + koff;
                *reinterpret_cast<__half2*>(base) = h0;
                *reinterpret_cast<__half2*>(base + 2) = h1;
            }
        } else if (MODE == 2) {
            float4 bb = *reinterpret_cast<const float4*>(bias + gn);
            __half2 h0 = __floats2half2_rn(gelu_exact(v.x + bb.x), gelu_exact(v.y + bb.y));
            __half2 h1 = __floats2half2_rn(gelu_exact(v.z + bb.z), gelu_exact(v.w + bb.w));
            __half2* dst = reinterpret_cast<__half2*>(g_hidh + (size_t)gm * 512 + gn);
            dst[0] = h0; dst[1] = h1;
        } else {
            float4 bb = *reinterpret_cast<const float4*>(bias + gn);
            float4 x1 = *reinterpret_cast<const float4*>(g_x1 + (size_t)gm * Dm + gn);
            v.x = x1.x + v.x + bb.x;
            v.y = x1.y + v.y + bb.y;
            v.z = x1.z + v.z + bb.z;
            v.w = x1.w + v.w + bb.w;
            *reinterpret_cast<float4*>(outp + (size_t)gm * Dm + gn) = v;
        }
    }
}

// ------------------------------- launch ---------------------------------
extern "C" void kernel_launch(void* const* d_in, const int* in_sizes, int n_in,
                              void* d_out, int out_size)
{
    const float* x      = (const float*)d_in[0];
    const int*   ef     = (const int*)  d_in[1];
    const int*   eg     = (const int*)  d_in[2];
    const float* kqv_w  = (const float*)d_in[3];
    const float* kqv_b  = (const float*)d_in[4];
    const float* a_f    = (const float*)d_in[5];
    const float* m_f    = (const float*)d_in[6];
    const float* p_f    = (const float*)d_in[7];
    const float* a_g    = (const float*)d_in[8];
    const float* m_g    = (const float*)d_in[9];
    const float* p_g    = (const float*)d_in[10];
    const float* out_w  = (const float*)d_in[11];
    const float* out_b  = (const float*)d_in[12];
    const float* skip   = (const float*)d_in[13];
    const float* ln1_g  = (const float*)d_in[14];
    const float* ln1_b  = (const float*)d_in[15];
    const float* ln2_g  = (const float*)d_in[16];
    const float* ln2_b  = (const float*)d_in[17];
    const float* w1     = (const float*)d_in[18];
    const float* b1     = (const float*)d_in[19];
    const float* w2     = (const float*)d_in[20];
    const float* b2     = (const float*)d_in[21];
    float* out = (float*)d_out;

    int N = in_sizes[0] / Dm;
    int E = in_sizes[1] / 2;
    if (N > NMAX) N = NMAX;
    if (E > EMAX) E = EMAX;

    int mtiles = (N + 127) / 128;
    int lnb = (N + 7) / 8;
    int zb  = (N + 255) / 256;

    cudaFuncSetAttribute(wgemm_kernel<0, 128>, cudaFuncAttributeMaxDynamicSharedMemorySize, SMEM_BYTES);
    cudaFuncSetAttribute(wgemm_kernel<1, 128>, cudaFuncAttributeMaxDynamicSharedMemorySize, SMEM_BYTES);
    cudaFuncSetAttribute(wgemm_kernel<2, 128>, cudaFuncAttributeMaxDynamicSharedMemorySize, SMEM_BYTES);
    cudaFuncSetAttribute(wgemm_kernel<3, 512>, cudaFuncAttributeMaxDynamicSharedMemorySize, SMEM_BYTES);

    // 0. fused setup: LN1 + prep_w + prep2 + zero_count
    setup_kernel<<<lnb + 320 + 576 + zb, 256>>>(x, ln1_g, ln1_b, kqv_w, kqv_b,
                                                a_f, m_f, p_f, a_g, m_g, p_g,
                                                out_w, w1, w2, N, lnb);
    // 1. fused projection GEMM: qh + interleaved kv
    wgemm_kernel<0, 128><<<dim3(mtiles, 5), 256, SMEM_BYTES>>>(
        nullptr, nullptr, nullptr, nullptr, nullptr, nullptr, N);
    // 2-4. CSR build by dst
    count_kernel<<<(2 * E + 255) / 256, 256>>>(ef, eg, E);
    scan_kernel<<<1, 1024>>>(N);
    scatter_kernel<<<(2 * E + 255) / 256, 256>>>(ef, eg, E);
    // 5. fused softmax + aggregation + gelu (8-deep gather pipeline)
    agg_kernel<<<(N + 7) / 8, 256>>>(N);
    // 6. out projection + skip-mix + residual + FUSED LN2 -> g_x1, g_xn2h
    wgemm_kernel<1, 128><<<dim3(mtiles, 1), 256, SMEM_BYTES>>>(
        out_b, x, skip, ln2_g, ln2_b, nullptr, N);
    // 7. FFN up + gelu -> g_hidh (fp16)
    wgemm_kernel<2, 128><<<dim3(mtiles, 4), 256, SMEM_BYTES>>>(
        b1, nullptr, nullptr, nullptr, nullptr, nullptr, N);
    // 8. FFN down + residual -> out
    wgemm_kernel<3, 512><<<dim3(mtiles, 1), 256, SMEM_BYTES>>>(
        b2, nullptr, nullptr, nullptr, nullptr, out, N);
}

// round 16
// speedup vs baseline: 1.3676x; 1.2787x over previous
#include <cuda_runtime.h>
#include <cuda_fp16.h>
#include <math.h>
#include <stdint.h>
#include <mma.h>

using namespace nvcuda;

// ---------------- problem-size constants (fixed dataset) ----------------
#define NMAX   50000
#define EMAX   300000
#define Dm     128
#define Hh     8
#define DHd    16

// ---------------- scratch (static device memory; no allocations) --------
__device__ __half g_xnh [NMAX * Dm];       // LN1 output, fp16
__device__ __half g_qh  [NMAX * Dm];       // q, fp16
// g_kv layout per node (512 halves): [f-block 256][g-block 256].
// Within a block, group q (q=0..31) owns halves [q*8, q*8+8):
//   [0:4) = k cols q*4..q*4+3,  [4:8) = v cols q*4..q*4+3.
__device__ __half g_kv  [NMAX * 512];
__device__ __half g_gacth[NMAX * Dm];
__device__ float  g_x1  [NMAX * Dm];
__device__ __half g_xn2h[NMAX * Dm];
__device__ __half g_hidh[NMAX * 4 * Dm];
__device__ __half g_WbigTh[640 * Dm];      // [n][k] fp16
__device__ __half g_outwTh[Dm * Dm];       // [n][k]
__device__ __half g_w1Th  [512 * Dm];      // [n][k]
__device__ __half g_w2Th  [Dm * 512];      // [n][k]
__device__ float  g_bbig [640];
__device__ int    g_count [NMAX];
__device__ int    g_offs  [NMAX + 1];
__device__ int    g_cursor[NMAX];
__device__ int    g_entries[2 * EMAX];
__device__ int    g_bsum  [256];

__device__ __forceinline__ float gelu_exact(float v) {
    return v * 0.5f * (1.0f + erff(v * 0.70710678118654752440f));
}

__device__ __forceinline__ uint32_t cvta_s(const void* p) {
    uint32_t a;
    asm("{ .reg .u64 t; cvta.to.shared.u64 t, %1; cvt.u32.u64 %0, t; }"
        : "=r"(a) : "l"(p));
    return a;
}

// ====== fused setup: LN1 | prep_w | prep2 | zero_count (grid-split) ======
__global__ void setup_kernel(const float* __restrict__ x,
                             const float* __restrict__ ln1_g,
                             const float* __restrict__ ln1_b,
                             const float* __restrict__ kqv_w,
                             const float* __restrict__ kqv_b,
                             const float* __restrict__ a_f,
                             const float* __restrict__ m_f,
                             const float* __restrict__ p_f,
                             const float* __restrict__ a_g,
                             const float* __restrict__ m_g,
                             const float* __restrict__ p_g,
                             const float* __restrict__ out_w,
                             const float* __restrict__ w1,
                             const float* __restrict__ w2,
                             int N, int lnb)
{
    int b = blockIdx.x;
    if (b < lnb) {
        // ---- LN1: one warp per row -> g_xnh ----
        int warp = ((b * 256) + threadIdx.x) >> 5;
        int lane = threadIdx.x & 31;
        if (warp >= N) return;
        float4 v = *reinterpret_cast<const float4*>(x + (size_t)warp * Dm + lane * 4);
        float s = v.x + v.y + v.z + v.w;
        #pragma unroll
        for (int o = 16; o; o >>= 1) s += __shfl_xor_sync(0xffffffffu, s, o);
        float mu = s * (1.0f / 128.0f);
        float dx = v.x - mu, dy = v.y - mu, dz = v.z - mu, dw = v.w - mu;
        float s2 = dx * dx + dy * dy + dz * dz + dw * dw;
        #pragma unroll
        for (int o = 16; o; o >>= 1) s2 += __shfl_xor_sync(0xffffffffu, s2, o);
        float r = rsqrtf(s2 * (1.0f / 128.0f) + 1e-5f);
        float4 gg = *reinterpret_cast<const float4*>(ln1_g + lane * 4);
        float4 bb = *reinterpret_cast<const float4*>(ln1_b + lane * 4);
        __half2 h0 = __floats2half2_rn(dx * r * gg.x + bb.x, dy * r * gg.y + bb.y);
        __half2 h1 = __floats2half2_rn(dz * r * gg.z + bb.z, dw * r * gg.w + bb.w);
        __half2* dst = reinterpret_cast<__half2*>(g_xnh + (size_t)warp * Dm + lane * 4);
        dst[0] = h0; dst[1] = h1;
        return;
    }
    b -= lnb;
    if (b < 320) {
        // ---- prep_w: fold relation mats into WbigTh/bbig ----
        int idx = b * 256 + threadIdx.x;
        if (idx >= Dm * 640) return;
        int n = idx % 640;
        int k = idx / 640;
        float val;
        if (n < 128) {
            val = kqv_w[k * 384 + 128 + n];
            if (k == 0) g_bbig[n] = kqv_b[128 + n];
        } else {
            int gsel = (n - 128) >> 7;
            int c = (n - 128) & 127;
            int h = c >> 4, f = c & 15;
            const float* mat; int srcoff; float scale = 1.0f;
            if      (gsel == 0) { mat = a_f; srcoff = 0;   scale = p_f[h] * 0.25f; }
            else if (gsel == 1) { mat = m_f; srcoff = 256; }
            else if (gsel == 2) { mat = a_g; srcoff = 0;   scale = p_g[h] * 0.25f; }
            else                { mat = m_g; srcoff = 256; }
            float s = 0.0f, bs = 0.0f;
            #pragma unroll
            for (int d = 0; d < 16; d++) {
                float w = mat[h * 256 + d * 16 + f];
                s  += kqv_w[k * 384 + srcoff + h * 16 + d] * w;
                bs += kqv_b[srcoff + h * 16 + d] * w;
            }
            val = s * scale;
            if (k == 0) g_bbig[n] = bs * scale;
        }
        g_WbigTh[n * Dm + k] = __float2half_rn(val);
        return;
    }
    b -= 320;
    if (b < 576) {
        // ---- prep2: transpose + fp16 other weights ----
        int idx = b * 256 + threadIdx.x;
        if (idx < 128 * 128) {
            int n = idx >> 7, k = idx & 127;
            g_outwTh[n * 128 + k] = __float2half_rn(out_w[k * 128 + n]);
        }
        idx -= 128 * 128;
        if (idx >= 0 && idx < 512 * 128) {
            int n = idx >> 7, k = idx & 127;
            g_w1Th[n * 128 + k] = __float2half_rn(w1[k * 512 + n]);
        }
        idx -= 512 * 128;
        if (idx >= 0 && idx < 128 * 512) {
            int n = idx >> 9, k = idx & 511;
            g_w2Th[n * 512 + k] = __float2half_rn(w2[k * 128 + n]);
        }
        return;
    }
    b -= 576;
    {
        int i = b * 256 + threadIdx.x;
        if (i < N) g_count[i] = 0;
    }
}

// ---------------- CSR build: count / 3-phase scan / scatter -------------
__global__ void count_kernel(const int* __restrict__ ef,
                             const int* __restrict__ eg, int E)
{
    int i = blockIdx.x * blockDim.x + threadIdx.x;
    if (i >= 2 * E) return;
    int dst = (i < E) ? ef[E + i] : eg[E + (i - E)];
    atomicAdd(&g_count[dst], 1);
}

// phase A: per-block sums of g_count (256 elems per block)
__global__ void scanA_kernel(int N)
{
    __shared__ int sm[256];
    int t = threadIdx.x;
    int i = blockIdx.x * 256 + t;
    sm[t] = (i < N) ? g_count[i] : 0;
    __syncthreads();
    #pragma unroll
    for (int off = 128; off; off >>= 1) {
        if (t < off) sm[t] += sm[t + off];
        __syncthreads();
    }
    if (t == 0) g_bsum[blockIdx.x] = sm[0];
}

// phase B: exclusive scan of block sums (single block), writes g_offs[N]
__global__ void scanB_kernel(int nb, int N)
{
    __shared__ int sm[256];
    int t = threadIdx.x;
    int v = (t < nb) ? g_bsum[t] : 0;
    sm[t] = v;
    __syncthreads();
    #pragma unroll
    for (int off = 1; off < 256; off <<= 1) {
        int u = (t >= off) ? sm[t - off] : 0;
        __syncthreads();
        sm[t] += u;
        __syncthreads();
    }
    if (t < nb) g_bsum[t] = sm[t] - v;      // exclusive block base
    if (t == nb - 1) g_offs[N] = sm[t];     // total
}

// phase C: in-block scan + base -> g_offs / g_cursor
__global__ void scanC_kernel(int N)
{
    __shared__ int sm[256];
    int t = threadIdx.x;
    int i = blockIdx.x * 256 + t;
    int v = (i < N) ? g_count[i] : 0;
    sm[t] = v;
    __syncthreads();
    #pragma unroll
    for (int off = 1; off < 256; off <<= 1) {
        int u = (t >= off) ? sm[t - off] : 0;
        __syncthreads();
        sm[t] += u;
        __syncthreads();
    }
    if (i < N) {
        int excl = sm[t] - v + g_bsum[blockIdx.x];
        g_offs[i] = excl;
        g_cursor[i] = excl;
    }
}

__global__ void scatter_kernel(const int* __restrict__ ef,
                               const int* __restrict__ eg, int E)
{
    int i = blockIdx.x * blockDim.x + threadIdx.x;
    if (i >= 2 * E) return;
    int src, dst, tbit;
    if (i < E) { src = ef[i];       dst = ef[E + i];       tbit = 0; }
    else       { int j = i - E; src = eg[j]; dst = eg[E + j]; tbit = 1 << 17; }
    int pos = atomicAdd(&g_cursor[dst], 1);
    g_entries[pos] = src | tbit;
}

// ------------- fused segment-softmax + aggregation + GELU ---------------
// One warp/node. 8-deep gather pipeline.
__global__ void agg_kernel(int N)
{
    int warp = (blockIdx.x * blockDim.x + threadIdx.x) >> 5;
    int lane = threadIdx.x & 31;
    if (warp >= N) return;
    uint2 qr = *reinterpret_cast<const uint2*>(g_qh + (size_t)warp * Dm + lane * 4);
    float2 qa = __half22float2(*reinterpret_cast<__half2*>(&qr.x));
    float2 qb = __half22float2(*reinterpret_cast<__half2*>(&qr.y));
    float4 q4 = make_float4(qa.x, qa.y, qb.x, qb.y);
    float4 acc = make_float4(0.f, 0.f, 0.f, 0.f);
    float denom = 0.0f;
    int beg = g_offs[warp], end = g_offs[warp + 1];
    int j = beg;
    int loff = lane * 8;
    for (; j + 8 <= end; j += 8) {
        int e[8];
        #pragma unroll
        for (int u = 0; u < 8; u++) e[u] = g_entries[j + u];
        uint4 r[8];
        #pragma unroll
        for (int u = 0; u < 8; u++) {
            const __half* p = g_kv + ((size_t)(e[u] & 0x1FFFF) << 9)
                                   + ((e[u] >> 9) & 256) + loff;
            r[u] = *reinterpret_cast<const uint4*>(p);
        }
        float ps[8];
        #pragma unroll
        for (int u = 0; u < 8; u++) {
            float2 ka = __half22float2(*reinterpret_cast<__half2*>(&r[u].x));
            float2 kb = __half22float2(*reinterpret_cast<__half2*>(&r[u].y));
            ps[u] = q4.x * ka.x + q4.y * ka.y + q4.z * kb.x + q4.w * kb.y;
        }
        #pragma unroll
        for (int u = 0; u < 8; u++)
            ps[u] += __shfl_xor_sync(0xffffffffu, ps[u], 1);
        #pragma unroll
        for (int u = 0; u < 8; u++)
            ps[u] += __shfl_xor_sync(0xffffffffu, ps[u], 2);
        #pragma unroll
        for (int u = 0; u < 8; u++) {
            float w = __expf(ps[u]);
            denom += w;
            float2 va = __half22float2(*reinterpret_cast<__half2*>(&r[u].z));
            float2 vb = __half22float2(*reinterpret_cast<__half2*>(&r[u].w));
            acc.x += w * va.x; acc.y += w * va.y;
            acc.z += w * vb.x; acc.w += w * vb.y;
        }
    }
    for (; j + 4 <= end; j += 4) {
        uint4 r[4];
        #pragma unroll
        for (int u = 0; u < 4; u++) {
            int e = g_entries[j + u];
            const __half* p = g_kv + ((size_t)(e & 0x1FFFF) << 9)
                                   + ((e >> 9) & 256) + loff;
            r[u] = *reinterpret_cast<const uint4*>(p);
        }
        float ps[4];
        #pragma unroll
        for (int u = 0; u < 4; u++) {
            float2 ka = __half22float2(*reinterpret_cast<__half2*>(&r[u].x));
            float2 kb = __half22float2(*reinterpret_cast<__half2*>(&r[u].y));
            ps[u] = q4.x * ka.x + q4.y * ka.y + q4.z * kb.x + q4.w * kb.y;
        }
        #pragma unroll
        for (int u = 0; u < 4; u++) {
            ps[u] += __shfl_xor_sync(0xffffffffu, ps[u], 1);
            ps[u] += __shfl_xor_sync(0xffffffffu, ps[u], 2);
        }
        #pragma unroll
        for (int u = 0; u < 4; u++) {
            float w = __expf(ps[u]);
            denom += w;
            float2 va = __half22float2(*reinterpret_cast<__half2*>(&r[u].z));
            float2 vb = __half22float2(*reinterpret_cast<__half2*>(&r[u].w));
            acc.x += w * va.x; acc.y += w * va.y;
            acc.z += w * vb.x; acc.w += w * vb.y;
        }
    }
    for (; j < end; j++) {
        int e = g_entries[j];
        const __half* p = g_kv + ((size_t)(e & 0x1FFFF) << 9)
                               + ((e >> 9) & 256) + loff;
        uint4 r = *reinterpret_cast<const uint4*>(p);
        float2 ka = __half22float2(*reinterpret_cast<__half2*>(&r.x));
        float2 kb = __half22float2(*reinterpret_cast<__half2*>(&r.y));
        float ps = q4.x * ka.x + q4.y * ka.y + q4.z * kb.x + q4.w * kb.y;
        ps += __shfl_xor_sync(0xffffffffu, ps, 1);
        ps += __shfl_xor_sync(0xffffffffu, ps, 2);
        float w = __expf(ps);
        denom += w;
        float2 va = __half22float2(*reinterpret_cast<__half2*>(&r.z));
        float2 vb = __half22float2(*reinterpret_cast<__half2*>(&r.w));
        acc.x += w * va.x; acc.y += w * va.y;
        acc.z += w * vb.x; acc.w += w * vb.y;
    }
    float rd = 1.0f / (denom + 1e-16f);
    __half2 o0 = __floats2half2_rn(gelu_exact(acc.x * rd), gelu_exact(acc.y * rd));
    __half2 o1 = __floats2half2_rn(gelu_exact(acc.z * rd), gelu_exact(acc.w * rd));
    __half2* dst = reinterpret_cast<__half2*>(g_gacth + (size_t)warp * Dm + lane * 4);
    dst[0] = o0; dst[1] = o1;
}

// =========== fp16 wmma GEMM: C = A[M,K] @ Bt[N,K]^T ======================
// (round-14 validated structure)
// MODE 0: A=g_xnh,  Bt=g_WbigTh -> qh(fp16) / interleaved g_kv  K=128, 5 nt
// MODE 1: A=g_gacth,Bt=g_outwTh -> g_x1 + FUSED LN2 -> g_xn2h  K=128
// MODE 2: A=g_xn2h, Bt=g_w1Th   -> g_hidh = gelu(C+b1) fp16   K=128, 4 nt
// MODE 3: A=g_hidh, Bt=g_w2Th   -> out = g_x1 + C + b2        K=512
#define APADH 136                          // halves per row (stride)
#define CPAD  132                          // floats per row for C overlay
#define SMEM_BYTES (2 * 128 * APADH * 2)   // 69632 bytes

template <int MODE, int K>
__global__ void __launch_bounds__(256, 2)
wgemm_kernel(const float* __restrict__ bias,
             const float* __restrict__ aux,    // MODE1: x
             const float* __restrict__ skip,   // MODE1 only
             const float* __restrict__ lng,    // MODE1: ln2 gamma
             const float* __restrict__ lnb,    // MODE1: ln2 beta
             float* __restrict__ outp,         // MODE3: d_out
             int M)
{
    extern __shared__ char smem[];
    __half* sA = reinterpret_cast<__half*>(smem);
    __half* sB = reinterpret_cast<__half*>(smem) + 128 * APADH;
    float*  sC = reinterpret_cast<float*>(smem);

    int tid = threadIdx.x;
    int wid = tid >> 5;
    int lane = tid & 31;
    int m0 = blockIdx.x * 128;
    int n0 = blockIdx.y * 128;

    int wm = (wid & 1) * 64;
    int wn = (wid >> 1) * 32;

    const __half* A;
    const __half* Bt;
    if      (MODE == 0) { A = g_xnh;   Bt = g_WbigTh; }
    else if (MODE == 1) { A = g_gacth; Bt = g_outwTh; }
    else if (MODE == 2) { A = g_xn2h;  Bt = g_w1Th;   }
    else                { A = g_hidh;  Bt = g_w2Th;   }

    wmma::fragment<wmma::accumulator, 16, 16, 16, float> acc[4][2];
    #pragma unroll
    for (int i = 0; i < 4; i++)
        #pragma unroll
        for (int j = 0; j < 2; j++)
            wmma::fill_fragment(acc[i][j], 0.0f);

    for (int kc = 0; kc < K; kc += 128) {
        #pragma unroll
        for (int i = tid; i < 128 * 16; i += 256) {
            int row = i >> 4, g8 = i & 15;
            int gm = m0 + row;
            uint32_t da = cvta_s(&sA[row * APADH + g8 * 8]);
            const __half* srcA = A + (size_t)gm * K + kc + g8 * 8;
            int szA = (gm < M) ? 16 : 0;
            asm volatile("cp.async.cg.shared.global [%0], [%1], 16, %2;"
                         :: "r"(da), "l"(srcA), "r"(szA));
            uint32_t db = cvta_s(&sB[row * APADH + g8 * 8]);
            const __half* srcB = Bt + (size_t)(n0 + row) * K + kc + g8 * 8;
            asm volatile("cp.async.cg.shared.global [%0], [%1], 16;"
                         :: "r"(db), "l"(srcB));
        }
        asm volatile("cp.async.commit_group;");
        asm volatile("cp.async.wait_group 0;" ::: "memory");
        __syncthreads();

        #pragma unroll
        for (int ks = 0; ks < 8; ks++) {
            wmma::fragment<wmma::matrix_b, 16, 16, 16, __half, wmma::col_major> bf[2];
            #pragma unroll
            for (int j = 0; j < 2; j++)
                wmma::load_matrix_sync(bf[j], &sB[(wn + j * 16) * APADH + ks * 16], APADH);
            #pragma unroll
            for (int i = 0; i < 4; i++) {
                wmma::fragment<wmma::matrix_a, 16, 16, 16, __half, wmma::row_major> af;
                wmma::load_matrix_sync(af, &sA[(wm + i * 16) * APADH + ks * 16], APADH);
                wmma::mma_sync(acc[i][0], af, bf[0], acc[i][0]);
                wmma::mma_sync(acc[i][1], af, bf[1], acc[i][1]);
            }
        }
        __syncthreads();
    }

    #pragma unroll
    for (int i = 0; i < 4; i++)
        #pragma unroll
        for (int j = 0; j < 2; j++)
            wmma::store_matrix_sync(&sC[(wm + i * 16) * CPAD + wn + j * 16],
                                    acc[i][j], CPAD, wmma::mem_row_major);
    __syncthreads();

    if (MODE == 1) {
        float sig = 1.0f / (1.0f + __expf(-skip[0]));
        float om = 1.0f - sig;
        float4 bb  = *reinterpret_cast<const float4*>(bias + lane * 4);
        float4 gg  = *reinterpret_cast<const float4*>(lng + lane * 4);
        float4 be  = *reinterpret_cast<const float4*>(lnb + lane * 4);
        for (int r = wid; r < 128; r += 8) {
            int gm = m0 + r;
            if (gm >= M) continue;
            float4 v = *reinterpret_cast<float4*>(&sC[r * CPAD + lane * 4]);
            float4 xv = *reinterpret_cast<const float4*>(aux + (size_t)gm * Dm + lane * 4);
            uint2 xr = *reinterpret_cast<const uint2*>(g_xnh + (size_t)gm * Dm + lane * 4);
            float2 xa = __half22float2(*reinterpret_cast<__half2*>(&xr.x));
            float2 xb = __half22float2(*reinterpret_cast<__half2*>(&xr.y));
            v.x = xv.x + sig * (v.x + bb.x) + om * xa.x;
            v.y = xv.y + sig * (v.y + bb.y) + om * xa.y;
            v.z = xv.z + sig * (v.z + bb.z) + om * xb.x;
            v.w = xv.w + sig * (v.w + bb.w) + om * xb.y;
            *reinterpret_cast<float4*>(g_x1 + (size_t)gm * Dm + lane * 4) = v;
            float s = v.x + v.y + v.z + v.w;
            #pragma unroll
            for (int o = 16; o; o >>= 1) s += __shfl_xor_sync(0xffffffffu, s, o);
            float mu = s * (1.0f / 128.0f);
            float dx = v.x - mu, dy = v.y - mu, dz = v.z - mu, dw = v.w - mu;
            float s2 = dx * dx + dy * dy + dz * dz + dw * dw;
            #pragma unroll
            for (int o = 16; o; o >>= 1) s2 += __shfl_xor_sync(0xffffffffu, s2, o);
            float rr = rsqrtf(s2 * (1.0f / 128.0f) + 1e-5f);
            __half2 h0 = __floats2half2_rn(dx * rr * gg.x + be.x, dy * rr * gg.y + be.y);
            __half2 h1 = __floats2half2_rn(dz * rr * gg.z + be.z, dw * rr * gg.w + be.w);
            __half2* dst = reinterpret_cast<__half2*>(g_xn2h + (size_t)gm * Dm + lane * 4);
            dst[0] = h0; dst[1] = h1;
        }
        return;
    }

    #pragma unroll
    for (int i = tid; i < 128 * 32; i += 256) {
        int row = i >> 5, q = i & 31;
        int gm = m0 + row;
        if (gm >= M) continue;
        float4 v = *reinterpret_cast<float4*>(&sC[row * CPAD + q * 4]);
        int gn = n0 + q * 4;
        if (MODE == 0) {
            float4 bb = *reinterpret_cast<const float4*>(g_bbig + gn);
            v.x += bb.x; v.y += bb.y; v.z += bb.z; v.w += bb.w;
            __half2 h0 = __floats2half2_rn(v.x, v.y);
            __half2 h1 = __floats2half2_rn(v.z, v.w);
            if (blockIdx.y == 0) {
                __half2* dst = reinterpret_cast<__half2*>(
                    g_qh + (size_t)gm * Dm + q * 4);
                dst[0] = h0; dst[1] = h1;
            } else {
                int type = blockIdx.y - 1;      // kf,vf,kg,vg
                int tb = (type >> 1) * 256;
                int koff = (type & 1) * 4;
                __half* base = g_kv + ((size_t)gm << 9) + tb + q * 8 + koff;
                *reinterpret_cast<__half2*>(base) = h0;
                *reinterpret_cast<__half2*>(base + 2) = h1;
            }
        } else if (MODE == 2) {
            float4 bb = *reinterpret_cast<const float4*>(bias + gn);
            __half2 h0 = __floats2half2_rn(gelu_exact(v.x + bb.x), gelu_exact(v.y + bb.y));
            __half2 h1 = __floats2half2_rn(gelu_exact(v.z + bb.z), gelu_exact(v.w + bb.w));
            __half2* dst = reinterpret_cast<__half2*>(g_hidh + (size_t)gm * 512 + gn);
            dst[0] = h0; dst[1] = h1;
        } else {
            float4 bb = *reinterpret_cast<const float4*>(bias + gn);
            float4 x1 = *reinterpret_cast<const float4*>(g_x1 + (size_t)gm * Dm + gn);
            v.x = x1.x + v.x + bb.x;
            v.y = x1.y + v.y + bb.y;
            v.z = x1.z + v.z + bb.z;
            v.w = x1.w + v.w + bb.w;
            *reinterpret_cast<float4*>(outp + (size_t)gm * Dm + gn) = v;
        }
    }
}

// ------------------------------- launch ---------------------------------
extern "C" void kernel_launch(void* const* d_in, const int* in_sizes, int n_in,
                              void* d_out, int out_size)
{
    const float* x      = (const float*)d_in[0];
    const int*   ef     = (const int*)  d_in[1];
    const int*   eg     = (const int*)  d_in[2];
    const float* kqv_w  = (const float*)d_in[3];
    const float* kqv_b  = (const float*)d_in[4];
    const float* a_f    = (const float*)d_in[5];
    const float* m_f    = (const float*)d_in[6];
    const float* p_f    = (const float*)d_in[7];
    const float* a_g    = (const float*)d_in[8];
    const float* m_g    = (const float*)d_in[9];
    const float* p_g    = (const float*)d_in[10];
    const float* out_w  = (const float*)d_in[11];
    const float* out_b  = (const float*)d_in[12];
    const float* skip   = (const float*)d_in[13];
    const float* ln1_g  = (const float*)d_in[14];
    const float* ln1_b  = (const float*)d_in[15];
    const float* ln2_g  = (const float*)d_in[16];
    const float* ln2_b  = (const float*)d_in[17];
    const float* w1     = (const float*)d_in[18];
    const float* b1     = (const float*)d_in[19];
    const float* w2     = (const float*)d_in[20];
    const float* b2     = (const float*)d_in[21];
    float* out = (float*)d_out;

    int N = in_sizes[0] / Dm;
    int E = in_sizes[1] / 2;
    if (N > NMAX) N = NMAX;
    if (E > EMAX) E = EMAX;

    int mtiles = (N + 127) / 128;
    int lnb = (N + 7) / 8;
    int zb  = (N + 255) / 256;
    int sb  = (N + 255) / 256;      // scan blocks (<=196 for N=50000)

    cudaFuncSetAttribute(wgemm_kernel<0, 128>, cudaFuncAttributeMaxDynamicSharedMemorySize, SMEM_BYTES);
    cudaFuncSetAttribute(wgemm_kernel<1, 128>, cudaFuncAttributeMaxDynamicSharedMemorySize, SMEM_BYTES);
    cudaFuncSetAttribute(wgemm_kernel<2, 128>, cudaFuncAttributeMaxDynamicSharedMemorySize, SMEM_BYTES);
    cudaFuncSetAttribute(wgemm_kernel<3, 512>, cudaFuncAttributeMaxDynamicSharedMemorySize, SMEM_BYTES);

    // 0. fused setup: LN1 + prep_w + prep2 + zero_count
    setup_kernel<<<lnb + 320 + 576 + zb, 256>>>(x, ln1_g, ln1_b, kqv_w, kqv_b,
                                                a_f, m_f, p_f, a_g, m_g, p_g,
                                                out_w, w1, w2, N, lnb);
    // 1. fused projection GEMM: qh + interleaved kv
    wgemm_kernel<0, 128><<<dim3(mtiles, 5), 256, SMEM_BYTES>>>(
        nullptr, nullptr, nullptr, nullptr, nullptr, nullptr, N);
    // 2-5. CSR build by dst (parallel 3-phase scan)
    count_kernel<<<(2 * E + 255) / 256, 256>>>(ef, eg, E);
    scanA_kernel<<<sb, 256>>>(N);
    scanB_kernel<<<1, 256>>>(sb, N);
    scanC_kernel<<<sb, 256>>>(N);
    scatter_kernel<<<(2 * E + 255) / 256, 256>>>(ef, eg, E);
    // 6. fused softmax + aggregation + gelu
    agg_kernel<<<(N + 7) / 8, 256>>>(N);
    // 7. out projection + skip-mix + residual + FUSED LN2 -> g_x1, g_xn2h
    wgemm_kernel<1, 128><<<dim3(mtiles, 1), 256, SMEM_BYTES>>>(
        out_b, x, skip, ln2_g, ln2_b, nullptr, N);
    // 8. FFN up + gelu -> g_hidh (fp16)
    wgemm_kernel<2, 128><<<dim3(mtiles, 4), 256, SMEM_BYTES>>>(
        b1, nullptr, nullptr, nullptr, nullptr, nullptr, N);
    // 9. FFN down + residual -> out
    wgemm_kernel<3, 512><<<dim3(mtiles, 1), 256, SMEM_BYTES>>>(
        b2, nullptr, nullptr, nullptr, nullptr, out, N);
}

// round 17
// speedup vs baseline: 1.3896x; 1.0161x over previous
#include <cuda_runtime.h>
#include <cuda_fp16.h>
#include <math.h>
#include <stdint.h>
#include <mma.h>

using namespace nvcuda;

// ---------------- problem-size constants (fixed dataset) ----------------
#define NMAX   50000
#define EMAX   300000
#define Dm     128
#define Hh     8
#define DHd    16

// ---------------- scratch (static device memory; no allocations) --------
__device__ __half g_xnh [NMAX * Dm];       // LN1 output, fp16
__device__ __half g_qh  [NMAX * Dm];       // q, fp16
// g_kv layout per node (512 halves): [f-block 256][g-block 256].
// Within a block, group q (q=0..31) owns halves [q*8, q*8+8):
//   [0:4) = k cols q*4..q*4+3,  [4:8) = v cols q*4..q*4+3.
__device__ __half g_kv  [NMAX * 512];
__device__ __half g_gacth[NMAX * Dm];
__device__ float  g_x1  [NMAX * Dm];
__device__ __half g_hidh[NMAX * 4 * Dm];
__device__ __half g_WbigTh[640 * Dm];      // [n][k] fp16
__device__ __half g_outwTh[Dm * Dm];       // [n][k]
__device__ __half g_w1Th  [512 * Dm];      // [n][k]
__device__ __half g_w2Th  [Dm * 512];      // [n][k]
__device__ float  g_bbig [640];
__device__ int    g_count [NMAX];
__device__ int    g_offs  [NMAX + 1];
__device__ int    g_cursor[NMAX];
__device__ int    g_entries[2 * EMAX];
__device__ int    g_bsum  [256];

__device__ __forceinline__ float gelu_exact(float v) {
    return v * 0.5f * (1.0f + erff(v * 0.70710678118654752440f));
}

__device__ __forceinline__ uint32_t cvta_s(const void* p) {
    uint32_t a;
    asm("{ .reg .u64 t; cvta.to.shared.u64 t, %1; cvt.u32.u64 %0, t; }"
        : "=r"(a) : "l"(p));
    return a;
}

// ====== fused setup: LN1 | prep_w | prep2 | zero_count (grid-split) ======
__global__ void setup_kernel(const float* __restrict__ x,
                             const float* __restrict__ ln1_g,
                             const float* __restrict__ ln1_b,
                             const float* __restrict__ kqv_w,
                             const float* __restrict__ kqv_b,
                             const float* __restrict__ a_f,
                             const float* __restrict__ m_f,
                             const float* __restrict__ p_f,
                             const float* __restrict__ a_g,
                             const float* __restrict__ m_g,
                             const float* __restrict__ p_g,
                             const float* __restrict__ out_w,
                             const float* __restrict__ w1,
                             const float* __restrict__ w2,
                             int N, int lnb)
{
    int b = blockIdx.x;
    if (b < lnb) {
        int warp = ((b * 256) + threadIdx.x) >> 5;
        int lane = threadIdx.x & 31;
        if (warp >= N) return;
        float4 v = *reinterpret_cast<const float4*>(x + (size_t)warp * Dm + lane * 4);
        float s = v.x + v.y + v.z + v.w;
        #pragma unroll
        for (int o = 16; o; o >>= 1) s += __shfl_xor_sync(0xffffffffu, s, o);
        float mu = s * (1.0f / 128.0f);
        float dx = v.x - mu, dy = v.y - mu, dz = v.z - mu, dw = v.w - mu;
        float s2 = dx * dx + dy * dy + dz * dz + dw * dw;
        #pragma unroll
        for (int o = 16; o; o >>= 1) s2 += __shfl_xor_sync(0xffffffffu, s2, o);
        float r = rsqrtf(s2 * (1.0f / 128.0f) + 1e-5f);
        float4 gg = *reinterpret_cast<const float4*>(ln1_g + lane * 4);
        float4 bb = *reinterpret_cast<const float4*>(ln1_b + lane * 4);
        __half2 h0 = __floats2half2_rn(dx * r * gg.x + bb.x, dy * r * gg.y + bb.y);
        __half2 h1 = __floats2half2_rn(dz * r * gg.z + bb.z, dw * r * gg.w + bb.w);
        __half2* dst = reinterpret_cast<__half2*>(g_xnh + (size_t)warp * Dm + lane * 4);
        dst[0] = h0; dst[1] = h1;
        return;
    }
    b -= lnb;
    if (b < 320) {
        int idx = b * 256 + threadIdx.x;
        if (idx >= Dm * 640) return;
        int n = idx % 640;
        int k = idx / 640;
        float val;
        if (n < 128) {
            val = kqv_w[k * 384 + 128 + n];
            if (k == 0) g_bbig[n] = kqv_b[128 + n];
        } else {
            int gsel = (n - 128) >> 7;
            int c = (n - 128) & 127;
            int h = c >> 4, f = c & 15;
            const float* mat; int srcoff; float scale = 1.0f;
            if      (gsel == 0) { mat = a_f; srcoff = 0;   scale = p_f[h] * 0.25f; }
            else if (gsel == 1) { mat = m_f; srcoff = 256; }
            else if (gsel == 2) { mat = a_g; srcoff = 0;   scale = p_g[h] * 0.25f; }
            else                { mat = m_g; srcoff = 256; }
            float s = 0.0f, bs = 0.0f;
            #pragma unroll
            for (int d = 0; d < 16; d++) {
                float w = mat[h * 256 + d * 16 + f];
                s  += kqv_w[k * 384 + srcoff + h * 16 + d] * w;
                bs += kqv_b[srcoff + h * 16 + d] * w;
            }
            val = s * scale;
            if (k == 0) g_bbig[n] = bs * scale;
        }
        g_WbigTh[n * Dm + k] = __float2half_rn(val);
        return;
    }
    b -= 320;
    if (b < 576) {
        int idx = b * 256 + threadIdx.x;
        if (idx < 128 * 128) {
            int n = idx >> 7, k = idx & 127;
            g_outwTh[n * 128 + k] = __float2half_rn(out_w[k * 128 + n]);
        }
        idx -= 128 * 128;
        if (idx >= 0 && idx < 512 * 128) {
            int n = idx >> 7, k = idx & 127;
            g_w1Th[n * 128 + k] = __float2half_rn(w1[k * 512 + n]);
        }
        idx -= 512 * 128;
        if (idx >= 0 && idx < 128 * 512) {
            int n = idx >> 9, k = idx & 511;
            g_w2Th[n * 512 + k] = __float2half_rn(w2[k * 128 + n]);
        }
        return;
    }
    b -= 576;
    {
        int i = b * 256 + threadIdx.x;
        if (i < N) g_count[i] = 0;
    }
}

// ---------------- CSR build: count / 3-phase scan / scatter -------------
__global__ void count_kernel(const int* __restrict__ ef,
                             const int* __restrict__ eg, int E)
{
    int i = blockIdx.x * blockDim.x + threadIdx.x;
    if (i >= 2 * E) return;
    int dst = (i < E) ? ef[E + i] : eg[E + (i - E)];
    atomicAdd(&g_count[dst], 1);
}

__global__ void scanA_kernel(int N)
{
    __shared__ int sm[256];
    int t = threadIdx.x;
    int i = blockIdx.x * 256 + t;
    sm[t] = (i < N) ? g_count[i] : 0;
    __syncthreads();
    #pragma unroll
    for (int off = 128; off; off >>= 1) {
        if (t < off) sm[t] += sm[t + off];
        __syncthreads();
    }
    if (t == 0) g_bsum[blockIdx.x] = sm[0];
}

__global__ void scanB_kernel(int nb, int N)
{
    __shared__ int sm[256];
    int t = threadIdx.x;
    int v = (t < nb) ? g_bsum[t] : 0;
    sm[t] = v;
    __syncthreads();
    #pragma unroll
    for (int off = 1; off < 256; off <<= 1) {
        int u = (t >= off) ? sm[t - off] : 0;
        __syncthreads();
        sm[t] += u;
        __syncthreads();
    }
    if (t < nb) g_bsum[t] = sm[t] - v;
    if (t == nb - 1) g_offs[N] = sm[t];
}

__global__ void scanC_kernel(int N)
{
    __shared__ int sm[256];
    int t = threadIdx.x;
    int i = blockIdx.x * 256 + t;
    int v = (i < N) ? g_count[i] : 0;
    sm[t] = v;
    __syncthreads();
    #pragma unroll
    for (int off = 1; off < 256; off <<= 1) {
        int u = (t >= off) ? sm[t - off] : 0;
        __syncthreads();
        sm[t] += u;
        __syncthreads();
    }
    if (i < N) {
        int excl = sm[t] - v + g_bsum[blockIdx.x];
        g_offs[i] = excl;
        g_cursor[i] = excl;
    }
}

__global__ void scatter_kernel(const int* __restrict__ ef,
                               const int* __restrict__ eg, int E)
{
    int i = blockIdx.x * blockDim.x + threadIdx.x;
    if (i >= 2 * E) return;
    int src, dst, tbit;
    if (i < E) { src = ef[i];       dst = ef[E + i];       tbit = 0; }
    else       { int j = i - E; src = eg[j]; dst = eg[E + j]; tbit = 1 << 17; }
    int pos = atomicAdd(&g_cursor[dst], 1);
    g_entries[pos] = src | tbit;
}

// ------------- fused segment-softmax + aggregation + GELU ---------------
__global__ void agg_kernel(int N)
{
    int warp = (blockIdx.x * blockDim.x + threadIdx.x) >> 5;
    int lane = threadIdx.x & 31;
    if (warp >= N) return;
    uint2 qr = *reinterpret_cast<const uint2*>(g_qh + (size_t)warp * Dm + lane * 4);
    float2 qa = __half22float2(*reinterpret_cast<__half2*>(&qr.x));
    float2 qb = __half22float2(*reinterpret_cast<__half2*>(&qr.y));
    float4 q4 = make_float4(qa.x, qa.y, qb.x, qb.y);
    float4 acc = make_float4(0.f, 0.f, 0.f, 0.f);
    float denom = 0.0f;
    int beg = g_offs[warp], end = g_offs[warp + 1];
    int j = beg;
    int loff = lane * 8;
    for (; j + 8 <= end; j += 8) {
        int e[8];
        #pragma unroll
        for (int u = 0; u < 8; u++) e[u] = g_entries[j + u];
        uint4 r[8];
        #pragma unroll
        for (int u = 0; u < 8; u++) {
            const __half* p = g_kv + ((size_t)(e[u] & 0x1FFFF) << 9)
                                   + ((e[u] >> 9) & 256) + loff;
            r[u] = *reinterpret_cast<const uint4*>(p);
        }
        float ps[8];
        #pragma unroll
        for (int u = 0; u < 8; u++) {
            float2 ka = __half22float2(*reinterpret_cast<__half2*>(&r[u].x));
            float2 kb = __half22float2(*reinterpret_cast<__half2*>(&r[u].y));
            ps[u] = q4.x * ka.x + q4.y * ka.y + q4.z * kb.x + q4.w * kb.y;
        }
        #pragma unroll
        for (int u = 0; u < 8; u++)
            ps[u] += __shfl_xor_sync(0xffffffffu, ps[u], 1);
        #pragma unroll
        for (int u = 0; u < 8; u++)
            ps[u] += __shfl_xor_sync(0xffffffffu, ps[u], 2);
        #pragma unroll
        for (int u = 0; u < 8; u++) {
            float w = __expf(ps[u]);
            denom += w;
            float2 va = __half22float2(*reinterpret_cast<__half2*>(&r[u].z));
            float2 vb = __half22float2(*reinterpret_cast<__half2*>(&r[u].w));
            acc.x += w * va.x; acc.y += w * va.y;
            acc.z += w * vb.x; acc.w += w * vb.y;
        }
    }
    for (; j + 4 <= end; j += 4) {
        uint4 r[4];
        #pragma unroll
        for (int u = 0; u < 4; u++) {
            int e = g_entries[j + u];
            const __half* p = g_kv + ((size_t)(e & 0x1FFFF) << 9)
                                   + ((e >> 9) & 256) + loff;
            r[u] = *reinterpret_cast<const uint4*>(p);
        }
        float ps[4];
        #pragma unroll
        for (int u = 0; u < 4; u++) {
            float2 ka = __half22float2(*reinterpret_cast<__half2*>(&r[u].x));
            float2 kb = __half22float2(*reinterpret_cast<__half2*>(&r[u].y));
            ps[u] = q4.x * ka.x + q4.y * ka.y + q4.z * kb.x + q4.w * kb.y;
        }
        #pragma unroll
        for (int u = 0; u < 4; u++) {
            ps[u] += __shfl_xor_sync(0xffffffffu, ps[u], 1);
            ps[u] += __shfl_xor_sync(0xffffffffu, ps[u], 2);
        }
        #pragma unroll
        for (int u = 0; u < 4; u++) {
            float w = __expf(ps[u]);
            denom += w;
            float2 va = __half22float2(*reinterpret_cast<__half2*>(&r[u].z));
            float2 vb = __half22float2(*reinterpret_cast<__half2*>(&r[u].w));
            acc.x += w * va.x; acc.y += w * va.y;
            acc.z += w * vb.x; acc.w += w * vb.y;
        }
    }
    for (; j < end; j++) {
        int e = g_entries[j];
        const __half* p = g_kv + ((size_t)(e & 0x1FFFF) << 9)
                               + ((e >> 9) & 256) + loff;
        uint4 r = *reinterpret_cast<const uint4*>(p);
        float2 ka = __half22float2(*reinterpret_cast<__half2*>(&r.x));
        float2 kb = __half22float2(*reinterpret_cast<__half2*>(&r.y));
        float ps = q4.x * ka.x + q4.y * ka.y + q4.z * kb.x + q4.w * kb.y;
        ps += __shfl_xor_sync(0xffffffffu, ps, 1);
        ps += __shfl_xor_sync(0xffffffffu, ps, 2);
        float w = __expf(ps);
        denom += w;
        float2 va = __half22float2(*reinterpret_cast<__half2*>(&r.z));
        float2 vb = __half22float2(*reinterpret_cast<__half2*>(&r.w));
        acc.x += w * va.x; acc.y += w * va.y;
        acc.z += w * vb.x; acc.w += w * vb.y;
    }
    float rd = 1.0f / (denom + 1e-16f);
    __half2 o0 = __floats2half2_rn(gelu_exact(acc.x * rd), gelu_exact(acc.y * rd));
    __half2 o1 = __floats2half2_rn(gelu_exact(acc.z * rd), gelu_exact(acc.w * rd));
    __half2* dst = reinterpret_cast<__half2*>(g_gacth + (size_t)warp * Dm + lane * 4);
    dst[0] = o0; dst[1] = o1;
}

// ---- common GEMM tile helpers ----
#define APADH 136                          // halves per row (stride)
#define CPAD  132                          // floats per row for C overlay
#define SMEM_BYTES (2 * 128 * APADH * 2)   // 69632 bytes
#define FUSE_SMEM  (3 * 128 * APADH * 2)   // 104448 bytes

// stage one 128x128 fp16 tile pair (A rows m0.., B rows n0..) in two
// cp.async groups (k halves 0..63 then 64..127).
template <int HALF>
__device__ __forceinline__ void stage_half(const __half* A, const __half* Bt,
                                           __half* sA, __half* sB,
                                           int m0, int n0, int kc, int K,
                                           int M, int tid)
{
    #pragma unroll
    for (int i = tid; i < 128 * 8; i += 256) {
        int row = i >> 3, g8 = (i & 7) + HALF * 8;
        int gm = m0 + row;
        uint32_t da = cvta_s(&sA[row * APADH + g8 * 8]);
        const __half* srcA = A + (size_t)gm * K + kc + g8 * 8;
        int szA = (gm < M) ? 16 : 0;
        asm volatile("cp.async.cg.shared.global [%0], [%1], 16, %2;"
                     :: "r"(da), "l"(srcA), "r"(szA));
        uint32_t db = cvta_s(&sB[row * APADH + g8 * 8]);
        const __half* srcB = Bt + (size_t)(n0 + row) * K + kc + g8 * 8;
        asm volatile("cp.async.cg.shared.global [%0], [%1], 16;"
                     :: "r"(db), "l"(srcB));
    }
    asm volatile("cp.async.commit_group;");
}

// 4 ksteps of wmma over k range [ks0, ks0+4)
__device__ __forceinline__ void mma_quad(
    wmma::fragment<wmma::accumulator, 16, 16, 16, float> acc[4][2],
    const __half* sA, const __half* sB, int wm, int wn, int ks0)
{
    #pragma unroll
    for (int ks = ks0; ks < ks0 + 4; ks++) {
        wmma::fragment<wmma::matrix_b, 16, 16, 16, __half, wmma::col_major> bf[2];
        #pragma unroll
        for (int j = 0; j < 2; j++)
            wmma::load_matrix_sync(bf[j], &sB[(wn + j * 16) * APADH + ks * 16], APADH);
        #pragma unroll
        for (int i = 0; i < 4; i++) {
            wmma::fragment<wmma::matrix_a, 16, 16, 16, __half, wmma::row_major> af;
            wmma::load_matrix_sync(af, &sA[(wm + i * 16) * APADH + ks * 16], APADH);
            wmma::mma_sync(acc[i][0], af, bf[0], acc[i][0]);
            wmma::mma_sync(acc[i][1], af, bf[1], acc[i][1]);
        }
    }
}

// =========== wgemm (MODE 0: projection, MODE 3: FFN-down) ================
template <int MODE, int K>
__global__ void __launch_bounds__(256, 2)
wgemm_kernel(const float* __restrict__ bias,
             float* __restrict__ outp,         // MODE3: d_out
             int M)
{
    extern __shared__ char smem[];
    __half* sA = reinterpret_cast<__half*>(smem);
    __half* sB = reinterpret_cast<__half*>(smem) + 128 * APADH;
    float*  sC = reinterpret_cast<float*>(smem);

    int tid = threadIdx.x;
    int wid = tid >> 5;
    int m0 = blockIdx.x * 128;
    int n0 = blockIdx.y * 128;

    int wm = (wid & 1) * 64;
    int wn = (wid >> 1) * 32;

    const __half* A;
    const __half* Bt;
    if (MODE == 0) { A = g_xnh;  Bt = g_WbigTh; }
    else           { A = g_hidh; Bt = g_w2Th;   }

    wmma::fragment<wmma::accumulator, 16, 16, 16, float> acc[4][2];
    #pragma unroll
    for (int i = 0; i < 4; i++)
        #pragma unroll
        for (int j = 0; j < 2; j++)
            wmma::fill_fragment(acc[i][j], 0.0f);

    for (int kc = 0; kc < K; kc += 128) {
        stage_half<0>(A, Bt, sA, sB, m0, n0, kc, K, M, tid);
        stage_half<1>(A, Bt, sA, sB, m0, n0, kc, K, M, tid);
        asm volatile("cp.async.wait_group 1;" ::: "memory");
        __syncthreads();
        mma_quad(acc, sA, sB, wm, wn, 0);
        asm volatile("cp.async.wait_group 0;" ::: "memory");
        __syncthreads();
        mma_quad(acc, sA, sB, wm, wn, 4);
        __syncthreads();
    }

    #pragma unroll
    for (int i = 0; i < 4; i++)
        #pragma unroll
        for (int j = 0; j < 2; j++)
            wmma::store_matrix_sync(&sC[(wm + i * 16) * CPAD + wn + j * 16],
                                    acc[i][j], CPAD, wmma::mem_row_major);
    __syncthreads();

    #pragma unroll
    for (int i = tid; i < 128 * 32; i += 256) {
        int row = i >> 5, q = i & 31;
        int gm = m0 + row;
        if (gm >= M) continue;
        float4 v = *reinterpret_cast<float4*>(&sC[row * CPAD + q * 4]);
        int gn = n0 + q * 4;
        if (MODE == 0) {
            float4 bb = *reinterpret_cast<const float4*>(g_bbig + gn);
            v.x += bb.x; v.y += bb.y; v.z += bb.z; v.w += bb.w;
            __half2 h0 = __floats2half2_rn(v.x, v.y);
            __half2 h1 = __floats2half2_rn(v.z, v.w);
            if (blockIdx.y == 0) {
                __half2* dst = reinterpret_cast<__half2*>(
                    g_qh + (size_t)gm * Dm + q * 4);
                dst[0] = h0; dst[1] = h1;
            } else {
                int type = blockIdx.y - 1;      // kf,vf,kg,vg
                int tb = (type >> 1) * 256;
                int koff = (type & 1) * 4;
                __half* base = g_kv + ((size_t)gm << 9) + tb + q * 8 + koff;
                *reinterpret_cast<__half2*>(base) = h0;
                *reinterpret_cast<__half2*>(base + 2) = h1;
            }
        } else {
            float4 bb = *reinterpret_cast<const float4*>(bias + gn);
            float4 x1 = *reinterpret_cast<const float4*>(g_x1 + (size_t)gm * Dm + gn);
            v.x = x1.x + v.x + bb.x;
            v.y = x1.y + v.y + bb.y;
            v.z = x1.z + v.z + bb.z;
            v.w = x1.w + v.w + bb.w;
            *reinterpret_cast<float4*>(outp + (size_t)gm * Dm + gn) = v;
        }
    }
}

// ====== fused out-proj + skip-mix + LN2 + FFN-up (MODE1+MODE2) ===========
// Phase 1: C1 = gacth @ outwT; x1 = x + sig*(C1+b)+(1-sig)*xnh -> g_x1;
//          LN2(x1) -> xn2h kept in smem tile sX (fp16, never hits global).
// Phase 2: for nc in 0..3: stage w1T chunk -> sB; hid = gelu(sX @ w1T + b1)
//          -> g_hidh columns nc*128..+127.
__global__ void __launch_bounds__(256, 2)
fuse1_kernel(const float* __restrict__ bias,    // out_b
             const float* __restrict__ aux,     // x
             const float* __restrict__ skip,
             const float* __restrict__ lng,
             const float* __restrict__ lnbp,
             const float* __restrict__ b1,
             int M)
{
    extern __shared__ char smem[];
    __half* sA = reinterpret_cast<__half*>(smem);
    __half* sB = sA + 128 * APADH;
    float*  sC = reinterpret_cast<float*>(smem);
    __half* sX = sA + 2 * 128 * APADH;

    int tid = threadIdx.x;
    int wid = tid >> 5;
    int lane = tid & 31;
    int m0 = blockIdx.x * 128;
    int wm = (wid & 1) * 64;
    int wn = (wid >> 1) * 32;

    wmma::fragment<wmma::accumulator, 16, 16, 16, float> acc[4][2];
    #pragma unroll
    for (int i = 0; i < 4; i++)
        #pragma unroll
        for (int j = 0; j < 2; j++)
            wmma::fill_fragment(acc[i][j], 0.0f);

    // ---- phase 1: out-proj GEMM ----
    stage_half<0>(g_gacth, g_outwTh, sA, sB, m0, 0, 0, 128, M, tid);
    stage_half<1>(g_gacth, g_outwTh, sA, sB, m0, 0, 0, 128, M, tid);
    asm volatile("cp.async.wait_group 1;" ::: "memory");
    __syncthreads();
    mma_quad(acc, sA, sB, wm, wn, 0);
    asm volatile("cp.async.wait_group 0;" ::: "memory");
    __syncthreads();
    mma_quad(acc, sA, sB, wm, wn, 4);
    __syncthreads();

    #pragma unroll
    for (int i = 0; i < 4; i++)
        #pragma unroll
        for (int j = 0; j < 2; j++)
            wmma::store_matrix_sync(&sC[(wm + i * 16) * CPAD + wn + j * 16],
                                    acc[i][j], CPAD, wmma::mem_row_major);
    __syncthreads();

    // ---- fused skip-mix + LN2 -> g_x1 (fp32) and sX (fp16) ----
    {
        float sig = 1.0f / (1.0f + __expf(-skip[0]));
        float om = 1.0f - sig;
        float4 bb  = *reinterpret_cast<const float4*>(bias + lane * 4);
        float4 gg  = *reinterpret_cast<const float4*>(lng + lane * 4);
        float4 be  = *reinterpret_cast<const float4*>(lnbp + lane * 4);
        for (int r = wid; r < 128; r += 8) {
            int gm = m0 + r;
            float4 v = make_float4(0.f, 0.f, 0.f, 0.f);
            if (gm < M) {
                v = *reinterpret_cast<float4*>(&sC[r * CPAD + lane * 4]);
                float4 xv = *reinterpret_cast<const float4*>(aux + (size_t)gm * Dm + lane * 4);
                uint2 xr = *reinterpret_cast<const uint2*>(g_xnh + (size_t)gm * Dm + lane * 4);
                float2 xa = __half22float2(*reinterpret_cast<__half2*>(&xr.x));
                float2 xb = __half22float2(*reinterpret_cast<__half2*>(&xr.y));
                v.x = xv.x + sig * (v.x + bb.x) + om * xa.x;
                v.y = xv.y + sig * (v.y + bb.y) + om * xa.y;
                v.z = xv.z + sig * (v.z + bb.z) + om * xb.x;
                v.w = xv.w + sig * (v.w + bb.w) + om * xb.y;
                *reinterpret_cast<float4*>(g_x1 + (size_t)gm * Dm + lane * 4) = v;
            }
            float s = v.x + v.y + v.z + v.w;
            #pragma unroll
            for (int o = 16; o; o >>= 1) s += __shfl_xor_sync(0xffffffffu, s, o);
            float mu = s * (1.0f / 128.0f);
            float dx = v.x - mu, dy = v.y - mu, dz = v.z - mu, dw = v.w - mu;
            float s2 = dx * dx + dy * dy + dz * dz + dw * dw;
            #pragma unroll
            for (int o = 16; o; o >>= 1) s2 += __shfl_xor_sync(0xffffffffu, s2, o);
            float rr = rsqrtf(s2 * (1.0f / 128.0f) + 1e-5f);
            __half2 h0 = __floats2half2_rn(dx * rr * gg.x + be.x, dy * rr * gg.y + be.y);
            __half2 h1 = __floats2half2_rn(dz * rr * gg.z + be.z, dw * rr * gg.w + be.w);
            __half2* dst = reinterpret_cast<__half2*>(&sX[r * APADH + lane * 4]);
            dst[0] = h0; dst[1] = h1;
        }
    }
    __syncthreads();

    // ---- phase 2: FFN-up over 4 n-chunks, A = sX resident in smem ----
    for (int nc = 0; nc < 4; nc++) {
        #pragma unroll
        for (int i = 0; i < 4; i++)
            #pragma unroll
            for (int j = 0; j < 2; j++)
                wmma::fill_fragment(acc[i][j], 0.0f);
        // stage w1T rows [nc*128, +128) into sB (two groups)
        #pragma unroll
        for (int h = 0; h < 2; h++) {
            #pragma unroll
            for (int i = tid; i < 128 * 8; i += 256) {
                int row = i >> 3, g8 = (i & 7) + h * 8;
                uint32_t db = cvta_s(&sB[row * APADH + g8 * 8]);
                const __half* srcB = g_w1Th + (size_t)(nc * 128 + row) * 128 + g8 * 8;
                asm volatile("cp.async.cg.shared.global [%0], [%1], 16;"
                             :: "r"(db), "l"(srcB));
            }
            asm volatile("cp.async.commit_group;");
        }
        asm volatile("cp.async.wait_group 1;" ::: "memory");
        __syncthreads();
        mma_quad(acc, sX, sB, wm, wn, 0);
        asm volatile("cp.async.wait_group 0;" ::: "memory");
        __syncthreads();
        mma_quad(acc, sX, sB, wm, wn, 4);
        __syncthreads();

        #pragma unroll
        for (int i = 0; i < 4; i++)
            #pragma unroll
            for (int j = 0; j < 2; j++)
                wmma::store_matrix_sync(&sC[(wm + i * 16) * CPAD + wn + j * 16],
                                        acc[i][j], CPAD, wmma::mem_row_major);
        __syncthreads();

        #pragma unroll
        for (int i = tid; i < 128 * 32; i += 256) {
            int row = i >> 5, q = i & 31;
            int gm = m0 + row;
            if (gm >= M) continue;
            float4 v = *reinterpret_cast<float4*>(&sC[row * CPAD + q * 4]);
            int gn = nc * 128 + q * 4;
            float4 bb = *reinterpret_cast<const float4*>(b1 + gn);
            __half2 h0 = __floats2half2_rn(gelu_exact(v.x + bb.x), gelu_exact(v.y + bb.y));
            __half2 h1 = __floats2half2_rn(gelu_exact(v.z + bb.z), gelu_exact(v.w + bb.w));
            __half2* dst = reinterpret_cast<__half2*>(g_hidh + (size_t)gm * 512 + gn);
            dst[0] = h0; dst[1] = h1;
        }
        __syncthreads();
    }
}

// ------------------------------- launch ---------------------------------
extern "C" void kernel_launch(void* const* d_in, const int* in_sizes, int n_in,
                              void* d_out, int out_size)
{
    const float* x      = (const float*)d_in[0];
    const int*   ef     = (const int*)  d_in[1];
    const int*   eg     = (const int*)  d_in[2];
    const float* kqv_w  = (const float*)d_in[3];
    const float* kqv_b  = (const float*)d_in[4];
    const float* a_f    = (const float*)d_in[5];
    const float* m_f    = (const float*)d_in[6];
    const float* p_f    = (const float*)d_in[7];
    const float* a_g    = (const float*)d_in[8];
    const float* m_g    = (const float*)d_in[9];
    const float* p_g    = (const float*)d_in[10];
    const float* out_w  = (const float*)d_in[11];
    const float* out_b  = (const float*)d_in[12];
    const float* skip   = (const float*)d_in[13];
    const float* ln1_g  = (const float*)d_in[14];
    const float* ln1_b  = (const float*)d_in[15];
    const float* ln2_g  = (const float*)d_in[16];
    const float* ln2_b  = (const float*)d_in[17];
    const float* w1     = (const float*)d_in[18];
    const float* b1     = (const float*)d_in[19];
    const float* w2     = (const float*)d_in[20];
    const float* b2     = (const float*)d_in[21];
    float* out = (float*)d_out;

    int N = in_sizes[0] / Dm;
    int E = in_sizes[1] / 2;
    if (N > NMAX) N = NMAX;
    if (E > EMAX) E = EMAX;

    int mtiles = (N + 127) / 128;
    int lnb = (N + 7) / 8;
    int zb  = (N + 255) / 256;
    int sb  = (N + 255) / 256;

    cudaFuncSetAttribute(wgemm_kernel<0, 128>, cudaFuncAttributeMaxDynamicSharedMemorySize, SMEM_BYTES);
    cudaFuncSetAttribute(wgemm_kernel<3, 512>, cudaFuncAttributeMaxDynamicSharedMemorySize, SMEM_BYTES);
    cudaFuncSetAttribute(fuse1_kernel, cudaFuncAttributeMaxDynamicSharedMemorySize, FUSE_SMEM);

    // 0. fused setup: LN1 + prep_w + prep2 + zero_count
    setup_kernel<<<lnb + 320 + 576 + zb, 256>>>(x, ln1_g, ln1_b, kqv_w, kqv_b,
                                                a_f, m_f, p_f, a_g, m_g, p_g,
                                                out_w, w1, w2, N, lnb);
    // 1. fused projection GEMM: qh + interleaved kv
    wgemm_kernel<0, 128><<<dim3(mtiles, 5), 256, SMEM_BYTES>>>(nullptr, nullptr, N);
    // 2-6. CSR build by dst (parallel 3-phase scan)
    count_kernel<<<(2 * E + 255) / 256, 256>>>(ef, eg, E);
    scanA_kernel<<<sb, 256>>>(N);
    scanB_kernel<<<1, 256>>>(sb, N);
    scanC_kernel<<<sb, 256>>>(N);
    scatter_kernel<<<(2 * E + 255) / 256, 256>>>(ef, eg, E);
    // 7. fused softmax + aggregation + gelu
    agg_kernel<<<(N + 7) / 8, 256>>>(N);
    // 8. fused out-proj + skip-mix + LN2 + FFN-up
    fuse1_kernel<<<mtiles, 256, FUSE_SMEM>>>(out_b, x, skip, ln2_g, ln2_b, b1, N);
    // 9. FFN down + residual -> out
    wgemm_kernel<3, 512><<<dim3(mtiles, 1), 256, SMEM_BYTES>>>(b2, out, N);
}